// round 1
// baseline (speedup 1.0000x reference)
#include <cuda_runtime.h>
#include <math.h>

#define BB 8
#define RR 128
#define TS 16384
#define NL 9
#define TT 128
#define KC 32
#define NTHR 512

// ---- scratch (device globals; no allocation allowed) ----
__device__ float g_h[2][BB * RR * TS];      // ping-pong residual stream [b][r][t]
__device__ float g_skip[BB * RR * TS];      // skip accumulator (pre-tanh of output1)
__device__ float g_wT[NL * 384 * 256];      // conv_w transposed: [l][tap*128+r][oc]
__device__ float g_w2T[NL * 128 * 256];     // [l][r][oc2]: oc2<128 -> out_w, oc2>=128 -> output1_w slice

__constant__ int c_dil[NL] = {1, 2, 4, 8, 16, 32, 64, 128, 256};

// ---- packed f32x2 helpers ----
__device__ __forceinline__ unsigned long long dup2(float w) {
    unsigned long long r;
    asm("mov.b64 %0, {%1, %1};" : "=l"(r) : "f"(w));
    return r;
}
__device__ __forceinline__ unsigned long long fma2(unsigned long long a,
                                                   unsigned long long b,
                                                   unsigned long long c) {
    unsigned long long d;
    asm("fma.rn.f32x2 %0, %1, %2, %3;" : "=l"(d) : "l"(a), "l"(b), "l"(c));
    return d;
}
__device__ __forceinline__ float2 unpk(unsigned long long v) {
    float2 f;
    asm("mov.b64 {%0, %1}, %2;" : "=f"(f.x), "=f"(f.y) : "l"(v));
    return f;
}
__device__ __forceinline__ float sigmoidf_(float x) {
    return 1.f / (1.f + __expf(-x));
}

// ---- weight re-layout (coalesced GEMM-friendly) ----
__global__ void k_prep(const float* __restrict__ conv_w,
                       const float* __restrict__ out_w,
                       const float* __restrict__ out1_w) {
    int idx = blockIdx.x * blockDim.x + threadIdx.x;
    const int n1 = NL * 384 * 256;
    if (idx < n1) {
        int oc = idx & 255;
        int kk = (idx >> 8) % 384;
        int l = idx / (384 * 256);
        int tap = kk >> 7;
        int r = kk & 127;
        // conv_w: [L][2R][R][K]
        g_wT[idx] = conv_w[(((l * 256 + oc) * 128 + r) * 3) + tap];
    } else {
        int j = idx - n1;
        if (j < NL * 128 * 256) {
            int oc = j & 255;
            int r = (j >> 8) & 127;
            int l = j / (128 * 256);
            float v;
            if (oc < 128)
                v = out_w[(l * 128 + oc) * 128 + r];              // out_w[l][oc][r][0]
            else
                v = out1_w[(oc - 128) * (RR * NL) + l * 128 + r]; // output1_w[ro][l*128+r]
            g_w2T[j] = v;
        }
    }
}

// ---- input layer + skip-accumulator init ----
__global__ void k_input(const float* __restrict__ x, const float* __restrict__ iw,
                        const float* __restrict__ ib, const float* __restrict__ ob1) {
    long idx = (long)blockIdx.x * blockDim.x + threadIdx.x;
    int t = (int)(idx % TS);
    long br = idx / TS;
    int r = (int)(br % RR);
    int b = (int)(br / RR);
    float v = tanhf(iw[r] * x[(long)b * TS + t] + ib[r]);
    g_h[0][idx] = v;
    g_skip[idx] = ob1[r];
}

// ---- fused layer: dilated gated conv + residual 1x1 + skip projection 1x1 ----
__global__ __launch_bounds__(NTHR, 1)
void k_layer(int l, int parity,
             const float* __restrict__ conv_b, const float* __restrict__ out_b) {
    extern __shared__ float smem[];
    float* sW = smem;                // [KC][256]  = 8192 floats
    float* sH = smem + 8192;         // [KC][TT]   = 4096 floats
    float* sZ = smem + 12288;        // [128][TT]  = 16384 floats

    const int tid = threadIdx.x;
    const int tx = tid & 15;         // t-subtile (8 t, = 4 packed pairs)
    const int ty = tid >> 4;         // 0..31 -> oc pairs (ty*4..+3, 128+ty*4..+3)
    const int b = blockIdx.y;
    const int t0 = blockIdx.x * TT;
    const int dil = c_dil[l];

    const float* __restrict__ hin = g_h[parity];
    float* __restrict__ hout = g_h[parity ^ 1];

    unsigned long long acc[8][4];
#pragma unroll
    for (int i = 0; i < 8; i++)
#pragma unroll
        for (int j = 0; j < 4; j++) acc[i][j] = 0ULL;

    const float* wbase = g_wT + l * 384 * 256;

    // ---------------- phase 1: pre[256][TT] = sum_{tap,r} W * h(t + (tap-2)*d)
    for (int c = 0; c < 12; c++) {
        {   // W chunk: 32 x 256 floats, fully contiguous
            const float4* src = (const float4*)(wbase + c * 32 * 256);
            float4* dst = (float4*)sW;
#pragma unroll
            for (int q = 0; q < 4; q++) dst[tid * 4 + q] = src[tid * 4 + q];
        }
        {   // H chunk: 32 r-rows x 128 t (tap-shifted, zero-padded on the left)
            int tap = c >> 2;
            int rbase = (c & 3) * 32;
            int row = tid >> 4;            // 0..31
            int col = (tid & 15) * 8;
            int toff = t0 + (tap - 2) * dil + col;
            const float* src = hin + ((long)(b * RR + rbase + row)) * TS;
            float* dst = &sH[row * TT + col];
#pragma unroll
            for (int j = 0; j < 8; j++) {
                int tg = toff + j;
                dst[j] = (tg >= 0) ? src[tg] : 0.f;
            }
        }
        __syncthreads();
        for (int k = 0; k < KC; k++) {
            float4 w0 = *(const float4*)&sW[k * 256 + ty * 4];
            float4 w1 = *(const float4*)&sW[k * 256 + 128 + ty * 4];
            ulonglong2 ha = *(const ulonglong2*)&sH[k * TT + tx * 8];
            ulonglong2 hb = *(const ulonglong2*)&sH[k * TT + tx * 8 + 4];
            unsigned long long hp[4] = {ha.x, ha.y, hb.x, hb.y};
            float wf0[4] = {w0.x, w0.y, w0.z, w0.w};
            float wf1[4] = {w1.x, w1.y, w1.z, w1.w};
#pragma unroll
            for (int i = 0; i < 4; i++) {
                unsigned long long wd = dup2(wf0[i]);
#pragma unroll
                for (int j = 0; j < 4; j++) acc[i][j] = fma2(wd, hp[j], acc[i][j]);
            }
#pragma unroll
            for (int i = 0; i < 4; i++) {
                unsigned long long wd = dup2(wf1[i]);
#pragma unroll
                for (int j = 0; j < 4; j++) acc[4 + i][j] = fma2(wd, hp[j], acc[4 + i][j]);
            }
        }
        __syncthreads();
    }

    // ---------------- gating (in-register pairing of c and c+128) -> sZ
#pragma unroll
    for (int i = 0; i < 4; i++) {
        int oc = ty * 4 + i;
        float bt = conv_b[l * 256 + oc];
        float bg = conv_b[l * 256 + 128 + oc];
#pragma unroll
        for (int j = 0; j < 4; j++) {
            float2 tv = unpk(acc[i][j]);
            float2 gv = unpk(acc[4 + i][j]);
            float z0 = tanhf(tv.x + bt) * sigmoidf_(gv.x + bg);
            float z1 = tanhf(tv.y + bt) * sigmoidf_(gv.y + bg);
            *(float2*)&sZ[oc * TT + tx * 8 + j * 2] = make_float2(z0, z1);
        }
    }
    __syncthreads();

    // ---------------- phase 2: [res(128); skipdelta(128)] = W2[256x128] @ z
#pragma unroll
    for (int i = 0; i < 8; i++)
#pragma unroll
        for (int j = 0; j < 4; j++) acc[i][j] = 0ULL;

    const float* w2base = g_w2T + l * 128 * 256;
    for (int c = 0; c < 4; c++) {
        {
            const float4* src = (const float4*)(w2base + c * 32 * 256);
            float4* dst = (float4*)sW;
#pragma unroll
            for (int q = 0; q < 4; q++) dst[tid * 4 + q] = src[tid * 4 + q];
        }
        __syncthreads();
        for (int k = 0; k < KC; k++) {
            int kg = c * 32 + k;
            float4 w0 = *(const float4*)&sW[k * 256 + ty * 4];
            float4 w1 = *(const float4*)&sW[k * 256 + 128 + ty * 4];
            ulonglong2 ha = *(const ulonglong2*)&sZ[kg * TT + tx * 8];
            ulonglong2 hb = *(const ulonglong2*)&sZ[kg * TT + tx * 8 + 4];
            unsigned long long hp[4] = {ha.x, ha.y, hb.x, hb.y};
            float wf0[4] = {w0.x, w0.y, w0.z, w0.w};
            float wf1[4] = {w1.x, w1.y, w1.z, w1.w};
#pragma unroll
            for (int i = 0; i < 4; i++) {
                unsigned long long wd = dup2(wf0[i]);
#pragma unroll
                for (int j = 0; j < 4; j++) acc[i][j] = fma2(wd, hp[j], acc[i][j]);
            }
#pragma unroll
            for (int i = 0; i < 4; i++) {
                unsigned long long wd = dup2(wf1[i]);
#pragma unroll
                for (int j = 0; j < 4; j++) acc[4 + i][j] = fma2(wd, hp[j], acc[4 + i][j]);
            }
        }
        __syncthreads();
    }

    // ---------------- epilogue: h_out = h_in + res + out_b ;  skip += skipdelta
#pragma unroll
    for (int i = 0; i < 4; i++) {
        int oc = ty * 4 + i;
        float rb = out_b[l * 128 + oc];
        long base = ((long)(b * RR + oc)) * TS + t0 + tx * 8;
#pragma unroll
        for (int j = 0; j < 4; j++) {
            float2 rv = unpk(acc[i][j]);
            float2 hv = *(const float2*)&hin[base + j * 2];
            float2 o;
            o.x = hv.x + rv.x + rb;
            o.y = hv.y + rv.y + rb;
            *(float2*)&hout[base + j * 2] = o;

            float2 sv = unpk(acc[4 + i][j]);
            float2 sp = *(float2*)&g_skip[base + j * 2];
            sp.x += sv.x;
            sp.y += sv.y;
            *(float2*)&g_skip[base + j * 2] = sp;
        }
    }
}

// ---- output head: out = output2_w @ tanh(skip) + output2_b ----
__global__ void k_out(const float* __restrict__ w2, const float* __restrict__ b2,
                      float* __restrict__ out) {
    int idx = blockIdx.x * blockDim.x + threadIdx.x;  // b*T + t
    int t = idx % TS;
    int b = idx / TS;
    const float* sp = g_skip + (long)b * RR * TS + t;
    float a = 0.f;
#pragma unroll 8
    for (int ro = 0; ro < RR; ro++) a += w2[ro] * tanhf(sp[(long)ro * TS]);
    out[idx] = a + b2[0];
}

extern "C" void kernel_launch(void* const* d_in, const int* in_sizes, int n_in,
                              void* d_out, int out_size) {
    const float* x       = (const float*)d_in[0];
    const float* input_w = (const float*)d_in[1];
    const float* input_b = (const float*)d_in[2];
    const float* conv_w  = (const float*)d_in[3];
    const float* conv_b  = (const float*)d_in[4];
    const float* out_w   = (const float*)d_in[5];
    const float* out_b   = (const float*)d_in[6];
    const float* out1_w  = (const float*)d_in[7];
    const float* out1_b  = (const float*)d_in[8];
    const float* out2_w  = (const float*)d_in[9];
    const float* out2_b  = (const float*)d_in[10];

    const int SMEM = 114688;  // 112 KB dynamic
    cudaFuncSetAttribute(k_layer, cudaFuncAttributeMaxDynamicSharedMemorySize, SMEM);

    int n_prep = NL * 384 * 256 + NL * 128 * 256;
    k_prep<<<(n_prep + 255) / 256, 256>>>(conv_w, out_w, out1_w);

    k_input<<<(BB * RR * TS) / 256, 256>>>(x, input_w, input_b, out1_b);

    int par = 0;
    for (int l = 0; l < NL; l++) {
        k_layer<<<dim3(TS / TT, BB), NTHR, SMEM>>>(l, par, conv_b, out_b);
        par ^= 1;
    }

    k_out<<<(BB * TS) / 256, 256>>>(out2_w, out2_b, (float*)d_out);
}

// round 2
// speedup vs baseline: 1.0016x; 1.0016x over previous
#include <cuda_runtime.h>
#include <math.h>

#define BB 8
#define RR 128
#define TS 16384
#define NL 9
#define TT 128
#define KC 32
#define NTHR 512

// ---- scratch (device globals; no allocation allowed) ----
__device__ float g_h[2][BB * RR * TS];      // ping-pong residual stream [b][r][t]
__device__ float g_skip[BB * RR * TS];      // skip accumulator (pre-tanh of output1)
__device__ float g_wT[NL * 384 * 256];      // conv_w transposed: [l][tap*128+r][oc]
__device__ float g_w2T[NL * 128 * 256];     // [l][r][oc2]: oc2<128 -> out_w, oc2>=128 -> output1_w slice

__constant__ int c_dil[NL] = {1, 2, 4, 8, 16, 32, 64, 128, 256};

// ---- packed f32x2 helpers ----
__device__ __forceinline__ unsigned long long dup2(float w) {
    unsigned long long r;
    asm("mov.b64 %0, {%1, %1};" : "=l"(r) : "f"(w));
    return r;
}
__device__ __forceinline__ unsigned long long fma2(unsigned long long a,
                                                   unsigned long long b,
                                                   unsigned long long c) {
    unsigned long long d;
    asm("fma.rn.f32x2 %0, %1, %2, %3;" : "=l"(d) : "l"(a), "l"(b), "l"(c));
    return d;
}
__device__ __forceinline__ float2 unpk(unsigned long long v) {
    float2 f;
    asm("mov.b64 {%0, %1}, %2;" : "=f"(f.x), "=f"(f.y) : "l"(v));
    return f;
}
__device__ __forceinline__ float sigmoidf_(float x) {
    return 1.f / (1.f + __expf(-x));
}

// ---- weight re-layout (coalesced GEMM-friendly) ----
__global__ void k_prep(const float* __restrict__ conv_w,
                       const float* __restrict__ out_w,
                       const float* __restrict__ out1_w) {
    int idx = blockIdx.x * blockDim.x + threadIdx.x;
    const int n1 = NL * 384 * 256;
    if (idx < n1) {
        int oc = idx & 255;
        int kk = (idx >> 8) % 384;
        int l = idx / (384 * 256);
        int tap = kk >> 7;
        int r = kk & 127;
        // conv_w: [L][2R][R][K]
        g_wT[idx] = conv_w[(((l * 256 + oc) * 128 + r) * 3) + tap];
    } else {
        int j = idx - n1;
        if (j < NL * 128 * 256) {
            int oc = j & 255;
            int r = (j >> 8) & 127;
            int l = j / (128 * 256);
            float v;
            if (oc < 128)
                v = out_w[(l * 128 + oc) * 128 + r];              // out_w[l][oc][r][0]
            else
                v = out1_w[(oc - 128) * (RR * NL) + l * 128 + r]; // output1_w[ro][l*128+r]
            g_w2T[j] = v;
        }
    }
}

// ---- input layer + skip-accumulator init ----
__global__ void k_input(const float* __restrict__ x, const float* __restrict__ iw,
                        const float* __restrict__ ib, const float* __restrict__ ob1) {
    long idx = (long)blockIdx.x * blockDim.x + threadIdx.x;
    int t = (int)(idx % TS);
    long br = idx / TS;
    int r = (int)(br % RR);
    int b = (int)(br / RR);
    float v = tanhf(iw[r] * x[(long)b * TS + t] + ib[r]);
    g_h[0][idx] = v;
    g_skip[idx] = ob1[r];
}

// ---- fused layer: dilated gated conv + residual 1x1 + skip projection 1x1 ----
__global__ __launch_bounds__(NTHR, 1)
void k_layer(int l, int parity,
             const float* __restrict__ conv_b, const float* __restrict__ out_b) {
    extern __shared__ float smem[];
    float* sW = smem;                // [KC][256]  = 8192 floats
    float* sH = smem + 8192;         // [KC][TT]   = 4096 floats
    float* sZ = smem + 12288;        // [128][TT]  = 16384 floats

    const int tid = threadIdx.x;
    const int tx = tid & 15;         // t-subtile (8 t, = 4 packed pairs)
    const int ty = tid >> 4;         // 0..31 -> oc pairs (ty*4..+3, 128+ty*4..+3)
    const int b = blockIdx.y;
    const int t0 = blockIdx.x * TT;
    const int dil = c_dil[l];

    const float* __restrict__ hin = g_h[parity];
    float* __restrict__ hout = g_h[parity ^ 1];

    unsigned long long acc[8][4];
#pragma unroll
    for (int i = 0; i < 8; i++)
#pragma unroll
        for (int j = 0; j < 4; j++) acc[i][j] = 0ULL;

    const float* wbase = g_wT + l * 384 * 256;

    // ---------------- phase 1: pre[256][TT] = sum_{tap,r} W * h(t + (tap-2)*d)
    for (int c = 0; c < 12; c++) {
        {   // W chunk: 32 x 256 floats, fully contiguous
            const float4* src = (const float4*)(wbase + c * 32 * 256);
            float4* dst = (float4*)sW;
#pragma unroll
            for (int q = 0; q < 4; q++) dst[tid * 4 + q] = src[tid * 4 + q];
        }
        {   // H chunk: 32 r-rows x 128 t (tap-shifted, zero-padded on the left)
            int tap = c >> 2;
            int rbase = (c & 3) * 32;
            int row = tid >> 4;            // 0..31
            int col = (tid & 15) * 8;
            int toff = t0 + (tap - 2) * dil + col;
            const float* src = hin + ((long)(b * RR + rbase + row)) * TS;
            float* dst = &sH[row * TT + col];
#pragma unroll
            for (int j = 0; j < 8; j++) {
                int tg = toff + j;
                dst[j] = (tg >= 0) ? src[tg] : 0.f;
            }
        }
        __syncthreads();
        for (int k = 0; k < KC; k++) {
            float4 w0 = *(const float4*)&sW[k * 256 + ty * 4];
            float4 w1 = *(const float4*)&sW[k * 256 + 128 + ty * 4];
            ulonglong2 ha = *(const ulonglong2*)&sH[k * TT + tx * 8];
            ulonglong2 hb = *(const ulonglong2*)&sH[k * TT + tx * 8 + 4];
            unsigned long long hp[4] = {ha.x, ha.y, hb.x, hb.y};
            float wf0[4] = {w0.x, w0.y, w0.z, w0.w};
            float wf1[4] = {w1.x, w1.y, w1.z, w1.w};
#pragma unroll
            for (int i = 0; i < 4; i++) {
                unsigned long long wd = dup2(wf0[i]);
#pragma unroll
                for (int j = 0; j < 4; j++) acc[i][j] = fma2(wd, hp[j], acc[i][j]);
            }
#pragma unroll
            for (int i = 0; i < 4; i++) {
                unsigned long long wd = dup2(wf1[i]);
#pragma unroll
                for (int j = 0; j < 4; j++) acc[4 + i][j] = fma2(wd, hp[j], acc[4 + i][j]);
            }
        }
        __syncthreads();
    }

    // ---------------- gating (in-register pairing of c and c+128) -> sZ
#pragma unroll
    for (int i = 0; i < 4; i++) {
        int oc = ty * 4 + i;
        float bt = conv_b[l * 256 + oc];
        float bg = conv_b[l * 256 + 128 + oc];
#pragma unroll
        for (int j = 0; j < 4; j++) {
            float2 tv = unpk(acc[i][j]);
            float2 gv = unpk(acc[4 + i][j]);
            float z0 = tanhf(tv.x + bt) * sigmoidf_(gv.x + bg);
            float z1 = tanhf(tv.y + bt) * sigmoidf_(gv.y + bg);
            *(float2*)&sZ[oc * TT + tx * 8 + j * 2] = make_float2(z0, z1);
        }
    }
    __syncthreads();

    // ---------------- phase 2: [res(128); skipdelta(128)] = W2[256x128] @ z
#pragma unroll
    for (int i = 0; i < 8; i++)
#pragma unroll
        for (int j = 0; j < 4; j++) acc[i][j] = 0ULL;

    const float* w2base = g_w2T + l * 128 * 256;
    for (int c = 0; c < 4; c++) {
        {
            const float4* src = (const float4*)(w2base + c * 32 * 256);
            float4* dst = (float4*)sW;
#pragma unroll
            for (int q = 0; q < 4; q++) dst[tid * 4 + q] = src[tid * 4 + q];
        }
        __syncthreads();
        for (int k = 0; k < KC; k++) {
            int kg = c * 32 + k;
            float4 w0 = *(const float4*)&sW[k * 256 + ty * 4];
            float4 w1 = *(const float4*)&sW[k * 256 + 128 + ty * 4];
            ulonglong2 ha = *(const ulonglong2*)&sZ[kg * TT + tx * 8];
            ulonglong2 hb = *(const ulonglong2*)&sZ[kg * TT + tx * 8 + 4];
            unsigned long long hp[4] = {ha.x, ha.y, hb.x, hb.y};
            float wf0[4] = {w0.x, w0.y, w0.z, w0.w};
            float wf1[4] = {w1.x, w1.y, w1.z, w1.w};
#pragma unroll
            for (int i = 0; i < 4; i++) {
                unsigned long long wd = dup2(wf0[i]);
#pragma unroll
                for (int j = 0; j < 4; j++) acc[i][j] = fma2(wd, hp[j], acc[i][j]);
            }
#pragma unroll
            for (int i = 0; i < 4; i++) {
                unsigned long long wd = dup2(wf1[i]);
#pragma unroll
                for (int j = 0; j < 4; j++) acc[4 + i][j] = fma2(wd, hp[j], acc[4 + i][j]);
            }
        }
        __syncthreads();
    }

    // ---------------- epilogue: h_out = h_in + res + out_b ;  skip += skipdelta
#pragma unroll
    for (int i = 0; i < 4; i++) {
        int oc = ty * 4 + i;
        float rb = out_b[l * 128 + oc];
        long base = ((long)(b * RR + oc)) * TS + t0 + tx * 8;
#pragma unroll
        for (int j = 0; j < 4; j++) {
            float2 rv = unpk(acc[i][j]);
            float2 hv = *(const float2*)&hin[base + j * 2];
            float2 o;
            o.x = hv.x + rv.x + rb;
            o.y = hv.y + rv.y + rb;
            *(float2*)&hout[base + j * 2] = o;

            float2 sv = unpk(acc[4 + i][j]);
            float2 sp = *(float2*)&g_skip[base + j * 2];
            sp.x += sv.x;
            sp.y += sv.y;
            *(float2*)&g_skip[base + j * 2] = sp;
        }
    }
}

// ---- output head: out = output2_w @ tanh(skip) + output2_b ----
__global__ void k_out(const float* __restrict__ w2, const float* __restrict__ b2,
                      float* __restrict__ out) {
    int idx = blockIdx.x * blockDim.x + threadIdx.x;  // b*T + t
    int t = idx % TS;
    int b = idx / TS;
    const float* sp = g_skip + (long)b * RR * TS + t;
    float a = 0.f;
#pragma unroll 8
    for (int ro = 0; ro < RR; ro++) a += w2[ro] * tanhf(sp[(long)ro * TS]);
    out[idx] = a + b2[0];
}

extern "C" void kernel_launch(void* const* d_in, const int* in_sizes, int n_in,
                              void* d_out, int out_size) {
    const float* x       = (const float*)d_in[0];
    const float* input_w = (const float*)d_in[1];
    const float* input_b = (const float*)d_in[2];
    const float* conv_w  = (const float*)d_in[3];
    const float* conv_b  = (const float*)d_in[4];
    const float* out_w   = (const float*)d_in[5];
    const float* out_b   = (const float*)d_in[6];
    const float* out1_w  = (const float*)d_in[7];
    const float* out1_b  = (const float*)d_in[8];
    const float* out2_w  = (const float*)d_in[9];
    const float* out2_b  = (const float*)d_in[10];

    const int SMEM = 114688;  // 112 KB dynamic
    cudaFuncSetAttribute(k_layer, cudaFuncAttributeMaxDynamicSharedMemorySize, SMEM);

    int n_prep = NL * 384 * 256 + NL * 128 * 256;
    k_prep<<<(n_prep + 255) / 256, 256>>>(conv_w, out_w, out1_w);

    k_input<<<(BB * RR * TS) / 256, 256>>>(x, input_w, input_b, out1_b);

    int par = 0;
    for (int l = 0; l < NL; l++) {
        k_layer<<<dim3(TS / TT, BB), NTHR, SMEM>>>(l, par, conv_b, out_b);
        par ^= 1;
    }

    k_out<<<(BB * TS) / 256, 256>>>(out2_w, out2_b, (float*)d_out);
}

// round 3
// speedup vs baseline: 1.0018x; 1.0003x over previous
#include <cuda_runtime.h>
#include <math.h>

#define BB 8
#define RR 128
#define TS 16384
#define NL 9
#define TT 128
#define KC 32
#define NTHR 512

// ---- scratch (device globals; no allocation allowed) ----
__device__ float g_h[2][BB * RR * TS];      // ping-pong residual stream [b][r][t]
__device__ float g_skip[BB * RR * TS];      // skip accumulator (pre-tanh of output1)
__device__ float g_wT[NL * 384 * 256];      // conv_w transposed: [l][tap*128+r][oc]
__device__ float g_w2T[NL * 128 * 256];     // [l][r][oc2]: oc2<128 -> out_w, oc2>=128 -> output1_w slice

__constant__ int c_dil[NL] = {1, 2, 4, 8, 16, 32, 64, 128, 256};

// ---- packed f32x2 helpers ----
__device__ __forceinline__ unsigned long long dup2(float w) {
    unsigned long long r;
    asm("mov.b64 %0, {%1, %1};" : "=l"(r) : "f"(w));
    return r;
}
__device__ __forceinline__ unsigned long long fma2(unsigned long long a,
                                                   unsigned long long b,
                                                   unsigned long long c) {
    unsigned long long d;
    asm("fma.rn.f32x2 %0, %1, %2, %3;" : "=l"(d) : "l"(a), "l"(b), "l"(c));
    return d;
}
__device__ __forceinline__ float2 unpk(unsigned long long v) {
    float2 f;
    asm("mov.b64 {%0, %1}, %2;" : "=f"(f.x), "=f"(f.y) : "l"(v));
    return f;
}
__device__ __forceinline__ float sigmoidf_(float x) {
    return 1.f / (1.f + __expf(-x));
}

// ---- weight re-layout (coalesced GEMM-friendly) ----
__global__ void k_prep(const float* __restrict__ conv_w,
                       const float* __restrict__ out_w,
                       const float* __restrict__ out1_w) {
    int idx = blockIdx.x * blockDim.x + threadIdx.x;
    const int n1 = NL * 384 * 256;
    if (idx < n1) {
        int oc = idx & 255;
        int kk = (idx >> 8) % 384;
        int l = idx / (384 * 256);
        int tap = kk >> 7;
        int r = kk & 127;
        // conv_w: [L][2R][R][K]
        g_wT[idx] = conv_w[(((l * 256 + oc) * 128 + r) * 3) + tap];
    } else {
        int j = idx - n1;
        if (j < NL * 128 * 256) {
            int oc = j & 255;
            int r = (j >> 8) & 127;
            int l = j / (128 * 256);
            float v;
            if (oc < 128)
                v = out_w[(l * 128 + oc) * 128 + r];              // out_w[l][oc][r][0]
            else
                v = out1_w[(oc - 128) * (RR * NL) + l * 128 + r]; // output1_w[ro][l*128+r]
            g_w2T[j] = v;
        }
    }
}

// ---- input layer + skip-accumulator init ----
__global__ void k_input(const float* __restrict__ x, const float* __restrict__ iw,
                        const float* __restrict__ ib, const float* __restrict__ ob1) {
    long idx = (long)blockIdx.x * blockDim.x + threadIdx.x;
    int t = (int)(idx % TS);
    long br = idx / TS;
    int r = (int)(br % RR);
    int b = (int)(br / RR);
    float v = tanhf(iw[r] * x[(long)b * TS + t] + ib[r]);
    g_h[0][idx] = v;
    g_skip[idx] = ob1[r];
}

// ---- fused layer: dilated gated conv + residual 1x1 + skip projection 1x1 ----
__global__ __launch_bounds__(NTHR, 1)
void k_layer(int l, int parity,
             const float* __restrict__ conv_b, const float* __restrict__ out_b) {
    extern __shared__ float smem[];
    float* sW = smem;                // [KC][256]  = 8192 floats
    float* sH = smem + 8192;         // [KC][TT]   = 4096 floats
    float* sZ = smem + 12288;        // [128][TT]  = 16384 floats

    const int tid = threadIdx.x;
    const int tx = tid & 15;         // t-subtile (8 t, = 4 packed pairs)
    const int ty = tid >> 4;         // 0..31 -> oc pairs (ty*4..+3, 128+ty*4..+3)
    const int b = blockIdx.y;
    const int t0 = blockIdx.x * TT;
    const int dil = c_dil[l];

    const float* __restrict__ hin = g_h[parity];
    float* __restrict__ hout = g_h[parity ^ 1];

    unsigned long long acc[8][4];
#pragma unroll
    for (int i = 0; i < 8; i++)
#pragma unroll
        for (int j = 0; j < 4; j++) acc[i][j] = 0ULL;

    const float* wbase = g_wT + l * 384 * 256;

    // ---------------- phase 1: pre[256][TT] = sum_{tap,r} W * h(t + (tap-2)*d)
    for (int c = 0; c < 12; c++) {
        {   // W chunk: 32 x 256 floats, fully contiguous
            const float4* src = (const float4*)(wbase + c * 32 * 256);
            float4* dst = (float4*)sW;
#pragma unroll
            for (int q = 0; q < 4; q++) dst[tid * 4 + q] = src[tid * 4 + q];
        }
        {   // H chunk: 32 r-rows x 128 t (tap-shifted, zero-padded on the left)
            int tap = c >> 2;
            int rbase = (c & 3) * 32;
            int row = tid >> 4;            // 0..31
            int col = (tid & 15) * 8;
            int toff = t0 + (tap - 2) * dil + col;
            const float* src = hin + ((long)(b * RR + rbase + row)) * TS;
            float* dst = &sH[row * TT + col];
#pragma unroll
            for (int j = 0; j < 8; j++) {
                int tg = toff + j;
                dst[j] = (tg >= 0) ? src[tg] : 0.f;
            }
        }
        __syncthreads();
        for (int k = 0; k < KC; k++) {
            float4 w0 = *(const float4*)&sW[k * 256 + ty * 4];
            float4 w1 = *(const float4*)&sW[k * 256 + 128 + ty * 4];
            ulonglong2 ha = *(const ulonglong2*)&sH[k * TT + tx * 8];
            ulonglong2 hb = *(const ulonglong2*)&sH[k * TT + tx * 8 + 4];
            unsigned long long hp[4] = {ha.x, ha.y, hb.x, hb.y};
            float wf0[4] = {w0.x, w0.y, w0.z, w0.w};
            float wf1[4] = {w1.x, w1.y, w1.z, w1.w};
#pragma unroll
            for (int i = 0; i < 4; i++) {
                unsigned long long wd = dup2(wf0[i]);
#pragma unroll
                for (int j = 0; j < 4; j++) acc[i][j] = fma2(wd, hp[j], acc[i][j]);
            }
#pragma unroll
            for (int i = 0; i < 4; i++) {
                unsigned long long wd = dup2(wf1[i]);
#pragma unroll
                for (int j = 0; j < 4; j++) acc[4 + i][j] = fma2(wd, hp[j], acc[4 + i][j]);
            }
        }
        __syncthreads();
    }

    // ---------------- gating (in-register pairing of c and c+128) -> sZ
#pragma unroll
    for (int i = 0; i < 4; i++) {
        int oc = ty * 4 + i;
        float bt = conv_b[l * 256 + oc];
        float bg = conv_b[l * 256 + 128 + oc];
#pragma unroll
        for (int j = 0; j < 4; j++) {
            float2 tv = unpk(acc[i][j]);
            float2 gv = unpk(acc[4 + i][j]);
            float z0 = tanhf(tv.x + bt) * sigmoidf_(gv.x + bg);
            float z1 = tanhf(tv.y + bt) * sigmoidf_(gv.y + bg);
            *(float2*)&sZ[oc * TT + tx * 8 + j * 2] = make_float2(z0, z1);
        }
    }
    __syncthreads();

    // ---------------- phase 2: [res(128); skipdelta(128)] = W2[256x128] @ z
#pragma unroll
    for (int i = 0; i < 8; i++)
#pragma unroll
        for (int j = 0; j < 4; j++) acc[i][j] = 0ULL;

    const float* w2base = g_w2T + l * 128 * 256;
    for (int c = 0; c < 4; c++) {
        {
            const float4* src = (const float4*)(w2base + c * 32 * 256);
            float4* dst = (float4*)sW;
#pragma unroll
            for (int q = 0; q < 4; q++) dst[tid * 4 + q] = src[tid * 4 + q];
        }
        __syncthreads();
        for (int k = 0; k < KC; k++) {
            int kg = c * 32 + k;
            float4 w0 = *(const float4*)&sW[k * 256 + ty * 4];
            float4 w1 = *(const float4*)&sW[k * 256 + 128 + ty * 4];
            ulonglong2 ha = *(const ulonglong2*)&sZ[kg * TT + tx * 8];
            ulonglong2 hb = *(const ulonglong2*)&sZ[kg * TT + tx * 8 + 4];
            unsigned long long hp[4] = {ha.x, ha.y, hb.x, hb.y};
            float wf0[4] = {w0.x, w0.y, w0.z, w0.w};
            float wf1[4] = {w1.x, w1.y, w1.z, w1.w};
#pragma unroll
            for (int i = 0; i < 4; i++) {
                unsigned long long wd = dup2(wf0[i]);
#pragma unroll
                for (int j = 0; j < 4; j++) acc[i][j] = fma2(wd, hp[j], acc[i][j]);
            }
#pragma unroll
            for (int i = 0; i < 4; i++) {
                unsigned long long wd = dup2(wf1[i]);
#pragma unroll
                for (int j = 0; j < 4; j++) acc[4 + i][j] = fma2(wd, hp[j], acc[4 + i][j]);
            }
        }
        __syncthreads();
    }

    // ---------------- epilogue: h_out = h_in + res + out_b ;  skip += skipdelta
#pragma unroll
    for (int i = 0; i < 4; i++) {
        int oc = ty * 4 + i;
        float rb = out_b[l * 128 + oc];
        long base = ((long)(b * RR + oc)) * TS + t0 + tx * 8;
#pragma unroll
        for (int j = 0; j < 4; j++) {
            float2 rv = unpk(acc[i][j]);
            float2 hv = *(const float2*)&hin[base + j * 2];
            float2 o;
            o.x = hv.x + rv.x + rb;
            o.y = hv.y + rv.y + rb;
            *(float2*)&hout[base + j * 2] = o;

            float2 sv = unpk(acc[4 + i][j]);
            float2 sp = *(float2*)&g_skip[base + j * 2];
            sp.x += sv.x;
            sp.y += sv.y;
            *(float2*)&g_skip[base + j * 2] = sp;
        }
    }
}

// ---- output head: out = output2_w @ tanh(skip) + output2_b ----
__global__ void k_out(const float* __restrict__ w2, const float* __restrict__ b2,
                      float* __restrict__ out) {
    int idx = blockIdx.x * blockDim.x + threadIdx.x;  // b*T + t
    int t = idx % TS;
    int b = idx / TS;
    const float* sp = g_skip + (long)b * RR * TS + t;
    float a = 0.f;
#pragma unroll 8
    for (int ro = 0; ro < RR; ro++) a += w2[ro] * tanhf(sp[(long)ro * TS]);
    out[idx] = a + b2[0];
}

extern "C" void kernel_launch(void* const* d_in, const int* in_sizes, int n_in,
                              void* d_out, int out_size) {
    const float* x       = (const float*)d_in[0];
    const float* input_w = (const float*)d_in[1];
    const float* input_b = (const float*)d_in[2];
    const float* conv_w  = (const float*)d_in[3];
    const float* conv_b  = (const float*)d_in[4];
    const float* out_w   = (const float*)d_in[5];
    const float* out_b   = (const float*)d_in[6];
    const float* out1_w  = (const float*)d_in[7];
    const float* out1_b  = (const float*)d_in[8];
    const float* out2_w  = (const float*)d_in[9];
    const float* out2_b  = (const float*)d_in[10];

    const int SMEM = 114688;  // 112 KB dynamic
    cudaFuncSetAttribute(k_layer, cudaFuncAttributeMaxDynamicSharedMemorySize, SMEM);

    int n_prep = NL * 384 * 256 + NL * 128 * 256;
    k_prep<<<(n_prep + 255) / 256, 256>>>(conv_w, out_w, out1_w);

    k_input<<<(BB * RR * TS) / 256, 256>>>(x, input_w, input_b, out1_b);

    int par = 0;
    for (int l = 0; l < NL; l++) {
        k_layer<<<dim3(TS / TT, BB), NTHR, SMEM>>>(l, par, conv_b, out_b);
        par ^= 1;
    }

    k_out<<<(BB * TS) / 256, 256>>>(out2_w, out2_b, (float*)d_out);
}

// round 6
// speedup vs baseline: 1.6501x; 1.6471x over previous
#include <cuda_runtime.h>
#include <math.h>
#include <stdint.h>

#define BB 8
#define RR 128
#define TS 16384
#define NL 9
#define NTHR 512

// h layout: [b][r][t]. SMEM B-tiles: rows padded to 136 floats.
#define PAD 136

// ---- global scratch ----
__device__ __align__(16) float g_h[2][(size_t)BB * RR * TS];
__device__ __align__(16) float g_skip[(size_t)BB * RR * TS];
// fragment-permuted weights, hi/lo split: [chunk][og(4)][ks(4)][mt(4)][lane(32)][e(4)]
__device__ __align__(16) float g_w1h[NL * 12 * 8192];
__device__ __align__(16) float g_w1l[NL * 12 * 8192];
__device__ __align__(16) float g_w2h[NL * 4 * 8192];
__device__ __align__(16) float g_w2l[NL * 4 * 8192];

__constant__ int c_dil[NL] = {1, 2, 4, 8, 16, 32, 64, 128, 256};

__device__ __forceinline__ float rtf32(float x) {
    uint32_t u;
    asm("cvt.rna.tf32.f32 %0, %1;" : "=r"(u) : "f"(x));
    return __uint_as_float(u);
}
__device__ __forceinline__ float sigmoidf_(float x) { return 1.f / (1.f + __expf(-x)); }

__device__ __forceinline__ void mma8(float* d, uint4 a, uint32_t b0, uint32_t b1) {
    asm volatile("mma.sync.aligned.m16n8k8.row.col.f32.tf32.tf32.f32 "
                 "{%0,%1,%2,%3}, {%4,%5,%6,%7}, {%8,%9}, {%0,%1,%2,%3};"
                 : "+f"(d[0]), "+f"(d[1]), "+f"(d[2]), "+f"(d[3])
                 : "r"(a.x), "r"(a.y), "r"(a.z), "r"(a.w), "r"(b0), "r"(b1));
}

// oc mapping: mt 0,1 -> low half, mt 2,3 -> +128.
// A-frag element (lane, e): row g+(e&1)*8, col q+(e>>1)*4.
__global__ void k_prep(const float* __restrict__ conv_w,
                       const float* __restrict__ out_w,
                       const float* __restrict__ out1_w) {
    int i = blockIdx.x * blockDim.x + threadIdx.x;
    const int n1 = NL * 12 * 8192;
    const int n2 = NL * 4 * 8192;
    if (i < n1) {
        int j = i & 8191;
        int ci = i >> 13;            // (l*3+tap)*4 + kc
        int kc = ci & 3;
        int tap = (ci >> 2) % 3;
        int l = ci / 12;
        int e = j & 3, lane = (j >> 2) & 31, mt = (j >> 7) & 3, ks = (j >> 9) & 3, og = (j >> 11) & 3;
        int g = lane >> 2, q = lane & 3;
        int oc = og * 32 + (mt & 1) * 16 + (mt >> 1) * 128 + g + (e & 1) * 8;
        int r = kc * 32 + ks * 8 + q + (e >> 1) * 4;
        float w = conv_w[((l * 256 + oc) * 128 + r) * 3 + tap];
        float hi = rtf32(w);
        g_w1h[i] = hi;
        g_w1l[i] = rtf32(w - hi);
    } else if (i < n1 + n2) {
        int ii = i - n1;
        int j = ii & 8191;
        int ci = ii >> 13;           // l*4 + kc
        int kc = ci & 3;
        int l = ci >> 2;
        int e = j & 3, lane = (j >> 2) & 31, mt = (j >> 7) & 3, ks = (j >> 9) & 3, og = (j >> 11) & 3;
        int g = lane >> 2, q = lane & 3;
        int m = og * 32 + (mt & 1) * 16 + (mt >> 1) * 128 + g + (e & 1) * 8;
        int r = kc * 32 + ks * 8 + q + (e >> 1) * 4;
        float w;
        if (m < 128) w = out_w[(l * 128 + m) * 128 + r];
        else         w = out1_w[(m - 128) * (RR * NL) + l * 128 + r];
        float hi = rtf32(w);
        g_w2h[ii] = hi;
        g_w2l[ii] = rtf32(w - hi);
    }
}

__global__ void k_input(const float* __restrict__ x, const float* __restrict__ iw,
                        const float* __restrict__ ib, const float* __restrict__ ob1) {
    size_t idx = (size_t)blockIdx.x * blockDim.x + threadIdx.x;
    int t = (int)(idx % TS);
    size_t br = idx / TS;
    int r = (int)(br % RR);
    int b = (int)(br / RR);
    float v = tanhf(iw[r] * x[(size_t)b * TS + t] + ib[r]);
    g_h[0][idx] = v;
    g_skip[idx] = ob1[r];
}

__global__ __launch_bounds__(NTHR, 1)
void k_layer(int l, int parity,
             const float* __restrict__ conv_b, const float* __restrict__ out_b) {
    extern __shared__ __align__(16) float sm[];
    float* sA0 = sm;                  // 32*136
    float* sA1 = sm + 4352;
    float* sZ  = sm + 8704;           // 128*136
    float* cb  = sm + 26112;          // 256
    float* ob  = cb + 256;            // 128

    const int tid = threadIdx.x;
    const int lane = tid & 31;
    const int wid = tid >> 5;
    const int wm = wid >> 2;          // oc group
    const int wn = wid & 3;           // t group
    const int g = lane >> 2;
    const int q = lane & 3;
    const int tcb = wn * 32 + g;

    const int b = blockIdx.y;
    const int t0 = blockIdx.x * 128;
    const int dil = c_dil[l];

    const float* __restrict__ hin = g_h[parity] + (size_t)b * RR * TS;
    float* __restrict__ hout = g_h[parity ^ 1] + (size_t)b * RR * TS;
    float* __restrict__ skp = g_skip + (size_t)b * RR * TS;

    if (tid < 256) cb[tid] = conv_b[l * 256 + tid];
    else if (tid < 384) ob[tid - 256] = out_b[l * 128 + (tid - 256)];

    const int fr = tid >> 4;              // fill row 0..31
    const int tseg = (tid & 15) * 8;      // fill t-seg

    float acc[4][4][4];
#pragma unroll
    for (int mt = 0; mt < 4; mt++)
#pragma unroll
        for (int nt = 0; nt < 4; nt++)
#pragma unroll
            for (int e = 0; e < 4; e++) acc[mt][nt][e] = 0.f;

    // ---- prologue: fill chunk 0 (raw fp32) ----
    {
        int shift = -2 * dil;            // tap 0
        const float* src = hin + (size_t)fr * TS + t0 + shift + tseg;
        int tb = t0 + shift + tseg;
        float* dst = sA0 + fr * PAD + tseg;
#pragma unroll
        for (int j = 0; j < 8; j++) dst[j] = (tb + j >= 0) ? src[j] : 0.f;
    }
    __syncthreads();

    // ---- phase 1: D1[256 oc][128 t], K = 384 (12 chunks) ----
    for (int c = 0; c < 12; c++) {
        float pv[8];
        const int have = (c < 11);
        if (have) {
            int c2 = c + 1;
            int tap2 = c2 >> 2, kc2 = c2 & 3;
            int shift = (tap2 - 2) * dil;
            const float* src = hin + (size_t)(kc2 * 32 + fr) * TS + t0 + shift + tseg;
            int tb = t0 + shift + tseg;
#pragma unroll
            for (int j = 0; j < 8; j++) pv[j] = (tb + j >= 0) ? src[j] : 0.f;
        }

        size_t choff = ((size_t)((l * 3 + (c >> 2)) * 4 + (c & 3))) * 8192 + wm * 2048;
        const float* wh = g_w1h + choff;
        const float* wl = g_w1l + choff;
        const float* bufp = (c & 1) ? sA1 : sA0;
#pragma unroll
        for (int ks = 0; ks < 4; ks++) {
            const float* br0 = bufp + (ks * 8 + q) * PAD + tcb;
            const float* br1 = br0 + 4 * PAD;
            uint32_t b0h[4], b0l[4], b1h[4], b1l[4];
#pragma unroll
            for (int nt = 0; nt < 4; nt++) {
                float v0 = br0[nt * 8], v1 = br1[nt * 8];
                float h0 = rtf32(v0), h1 = rtf32(v1);
                b0h[nt] = __float_as_uint(h0);
                b1h[nt] = __float_as_uint(h1);
                b0l[nt] = __float_as_uint(rtf32(v0 - h0));
                b1l[nt] = __float_as_uint(rtf32(v1 - h1));
            }
#pragma unroll
            for (int mt = 0; mt < 4; mt++) {
                uint4 ah = ((const uint4*)(wh + ks * 512 + mt * 128))[lane];
                uint4 al = ((const uint4*)(wl + ks * 512 + mt * 128))[lane];
#pragma unroll
                for (int nt = 0; nt < 4; nt++) {
                    mma8(acc[mt][nt], ah, b0h[nt], b1h[nt]);
                    mma8(acc[mt][nt], ah, b0l[nt], b1l[nt]);
                    mma8(acc[mt][nt], al, b0h[nt], b1h[nt]);
                }
            }
        }

        if (have) {
            float* dst = ((c + 1) & 1 ? sA1 : sA0) + fr * PAD + tseg;
#pragma unroll
            for (int j = 0; j < 8; j++) dst[j] = pv[j];
        }
        __syncthreads();
    }

    // ---- epilogue 1: gate in-register -> z tile (raw fp32) ----
#pragma unroll
    for (int mt = 0; mt < 2; mt++) {
        int zc = wm * 32 + mt * 16 + g;
        float bt0 = cb[zc], bg0 = cb[128 + zc];
        float bt8 = cb[zc + 8], bg8 = cb[128 + zc + 8];
#pragma unroll
        for (int nt = 0; nt < 4; nt++) {
            int tc = wn * 32 + nt * 8 + 2 * q;
            float z0 = tanhf(acc[mt][nt][0] + bt0) * sigmoidf_(acc[mt + 2][nt][0] + bg0);
            float z1 = tanhf(acc[mt][nt][1] + bt0) * sigmoidf_(acc[mt + 2][nt][1] + bg0);
            *(float2*)(sZ + zc * PAD + tc) = make_float2(z0, z1);
            float z2 = tanhf(acc[mt][nt][2] + bt8) * sigmoidf_(acc[mt + 2][nt][2] + bg8);
            float z3 = tanhf(acc[mt][nt][3] + bt8) * sigmoidf_(acc[mt + 2][nt][3] + bg8);
            *(float2*)(sZ + (zc + 8) * PAD + tc) = make_float2(z2, z3);
        }
    }
    __syncthreads();

    // ---- phase 2: [res;skip][t] = W2 @ z, K = 128 (4 chunks) ----
#pragma unroll
    for (int mt = 0; mt < 4; mt++)
#pragma unroll
        for (int nt = 0; nt < 4; nt++)
#pragma unroll
            for (int e = 0; e < 4; e++) acc[mt][nt][e] = 0.f;

    for (int kc = 0; kc < 4; kc++) {
        size_t choff = (size_t)(l * 4 + kc) * 8192 + wm * 2048;
        const float* wh = g_w2h + choff;
        const float* wl = g_w2l + choff;
#pragma unroll
        for (int ks = 0; ks < 4; ks++) {
            const float* br0 = sZ + (kc * 32 + ks * 8 + q) * PAD + tcb;
            const float* br1 = br0 + 4 * PAD;
            uint32_t b0h[4], b0l[4], b1h[4], b1l[4];
#pragma unroll
            for (int nt = 0; nt < 4; nt++) {
                float v0 = br0[nt * 8], v1 = br1[nt * 8];
                float h0 = rtf32(v0), h1 = rtf32(v1);
                b0h[nt] = __float_as_uint(h0);
                b1h[nt] = __float_as_uint(h1);
                b0l[nt] = __float_as_uint(rtf32(v0 - h0));
                b1l[nt] = __float_as_uint(rtf32(v1 - h1));
            }
#pragma unroll
            for (int mt = 0; mt < 4; mt++) {
                uint4 ah = ((const uint4*)(wh + ks * 512 + mt * 128))[lane];
                uint4 al = ((const uint4*)(wl + ks * 512 + mt * 128))[lane];
#pragma unroll
                for (int nt = 0; nt < 4; nt++) {
                    mma8(acc[mt][nt], ah, b0h[nt], b1h[nt]);
                    mma8(acc[mt][nt], ah, b0l[nt], b1l[nt]);
                    mma8(acc[mt][nt], al, b0h[nt], b1h[nt]);
                }
            }
        }
    }

    // ---- epilogue 2: h_out = h_in + res + out_b ; skip += delta ----
#pragma unroll
    for (int mt = 0; mt < 2; mt++) {
        int r0 = wm * 32 + mt * 16 + g;
        float ob0 = ob[r0], ob8 = ob[r0 + 8];
#pragma unroll
        for (int nt = 0; nt < 4; nt++) {
            int tc = wn * 32 + nt * 8 + 2 * q;
            size_t ix = (size_t)r0 * TS + t0 + tc;
            size_t ix8 = ix + (size_t)8 * TS;

            float2 hv = *(const float2*)(hin + ix);
            *(float2*)(hout + ix) = make_float2(hv.x + acc[mt][nt][0] + ob0,
                                                hv.y + acc[mt][nt][1] + ob0);
            float2 hv8 = *(const float2*)(hin + ix8);
            *(float2*)(hout + ix8) = make_float2(hv8.x + acc[mt][nt][2] + ob8,
                                                 hv8.y + acc[mt][nt][3] + ob8);

            float2 sv = *(const float2*)(skp + ix);
            sv.x += acc[mt + 2][nt][0];
            sv.y += acc[mt + 2][nt][1];
            *(float2*)(skp + ix) = sv;
            float2 sv8 = *(const float2*)(skp + ix8);
            sv8.x += acc[mt + 2][nt][2];
            sv8.y += acc[mt + 2][nt][3];
            *(float2*)(skp + ix8) = sv8;
        }
    }
}

__global__ void k_out(const float* __restrict__ w2, const float* __restrict__ b2,
                      float* __restrict__ out) {
    int idx = blockIdx.x * blockDim.x + threadIdx.x;  // b*T + t
    int t = idx % TS;
    int b = idx / TS;
    const float* sp = g_skip + (size_t)b * RR * TS + t;
    float a = 0.f;
#pragma unroll 8
    for (int ro = 0; ro < RR; ro++) a += w2[ro] * tanhf(sp[(size_t)ro * TS]);
    out[idx] = a + b2[0];
}

extern "C" void kernel_launch(void* const* d_in, const int* in_sizes, int n_in,
                              void* d_out, int out_size) {
    const float* x       = (const float*)d_in[0];
    const float* input_w = (const float*)d_in[1];
    const float* input_b = (const float*)d_in[2];
    const float* conv_w  = (const float*)d_in[3];
    const float* conv_b  = (const float*)d_in[4];
    const float* out_w   = (const float*)d_in[5];
    const float* out_b   = (const float*)d_in[6];
    const float* out1_w  = (const float*)d_in[7];
    const float* out1_b  = (const float*)d_in[8];
    const float* out2_w  = (const float*)d_in[9];
    const float* out2_b  = (const float*)d_in[10];

    const int SMEM = 26496 * 4;  // 105984 bytes
    cudaFuncSetAttribute(k_layer, cudaFuncAttributeMaxDynamicSharedMemorySize, SMEM);

    int n_prep = NL * 12 * 8192 + NL * 4 * 8192;
    k_prep<<<(n_prep + 255) / 256, 256>>>(conv_w, out_w, out1_w);
    k_input<<<(BB * RR * TS) / 256, 256>>>(x, input_w, input_b, out1_b);

    int par = 0;
    for (int l = 0; l < NL; l++) {
        k_layer<<<dim3(TS / 128, BB), NTHR, SMEM>>>(l, par, conv_b, out_b);
        par ^= 1;
    }
    k_out<<<(BB * TS) / 256, 256>>>(out2_w, out2_b, (float*)d_out);
}

// round 7
// speedup vs baseline: 2.6200x; 1.5878x over previous
#include <cuda_runtime.h>
#include <cuda_fp16.h>
#include <math.h>
#include <stdint.h>

#define BB 8
#define RR 128
#define TS 16384
#define NL 9
#define NTHR 512

// h layout: [b][r][t]. SMEM tiles: rows padded to 132 floats (PAD%16==4 -> conflict-free
// for the m16n8k16 B-fragment row pattern 2q/2q+1/2q+8/2q+9).
#define PAD 132

// ---- global scratch ----
__device__ __align__(16) float g_h[2][(size_t)BB * RR * TS];
__device__ __align__(16) float g_skip[(size_t)BB * RR * TS];
// fragment-permuted fp16 weights, hi/lo split:
// w1: [l*3+tap][kc][og(4)][ks(2)][mt(4)][lane(32)][e(8 halfs)]
__device__ __align__(16) __half g_w1h[NL * 12 * 8192];
__device__ __align__(16) __half g_w1l[NL * 12 * 8192];
__device__ __align__(16) __half g_w2h[NL * 4 * 8192];
__device__ __align__(16) __half g_w2l[NL * 4 * 8192];

__constant__ int c_dil[NL] = {1, 2, 4, 8, 16, 32, 64, 128, 256};

__device__ __forceinline__ float sigmoidf_(float x) { return 1.f / (1.f + __expf(-x)); }

__device__ __forceinline__ void mma16(float* d, uint4 a, uint32_t b0, uint32_t b1) {
    asm volatile("mma.sync.aligned.m16n8k16.row.col.f32.f16.f16.f32 "
                 "{%0,%1,%2,%3}, {%4,%5,%6,%7}, {%8,%9}, {%0,%1,%2,%3};"
                 : "+f"(d[0]), "+f"(d[1]), "+f"(d[2]), "+f"(d[3])
                 : "r"(a.x), "r"(a.y), "r"(a.z), "r"(a.w), "r"(b0), "r"(b1));
}

// A-frag (f16 m16n8k16) element e in 0..7:  row = g + ((e>>1)&1)*8 ;  k = 2q + (e&1) + (e>>2)*8
// oc mapping: mt 0,1 -> low half, mt 2,3 -> +128.
__global__ void k_prep(const float* __restrict__ conv_w,
                       const float* __restrict__ out_w,
                       const float* __restrict__ out1_w) {
    int i = blockIdx.x * blockDim.x + threadIdx.x;
    const int n1 = NL * 12 * 8192;
    const int n2 = NL * 4 * 8192;
    if (i < n1) {
        int j = i & 8191;
        int ci = i >> 13;            // (l*3+tap)*4 + kc
        int kc = ci & 3;
        int tap = (ci >> 2) % 3;
        int l = ci / 12;
        int e = j & 7, lane = (j >> 3) & 31, mt = (j >> 8) & 3, ks = (j >> 10) & 1, og = (j >> 11) & 3;
        int g = lane >> 2, q = lane & 3;
        int oc = og * 32 + (mt & 1) * 16 + (mt >> 1) * 128 + g + ((e >> 1) & 1) * 8;
        int r = kc * 32 + ks * 16 + 2 * q + (e & 1) + (e >> 2) * 8;
        float w = conv_w[((l * 256 + oc) * 128 + r) * 3 + tap];
        __half hi = __float2half_rn(w);
        g_w1h[i] = hi;
        g_w1l[i] = __float2half_rn(w - __half2float(hi));
    } else if (i < n1 + n2) {
        int ii = i - n1;
        int j = ii & 8191;
        int ci = ii >> 13;           // l*4 + kc
        int kc = ci & 3;
        int l = ci >> 2;
        int e = j & 7, lane = (j >> 3) & 31, mt = (j >> 8) & 3, ks = (j >> 10) & 1, og = (j >> 11) & 3;
        int g = lane >> 2, q = lane & 3;
        int m = og * 32 + (mt & 1) * 16 + (mt >> 1) * 128 + g + ((e >> 1) & 1) * 8;
        int r = kc * 32 + ks * 16 + 2 * q + (e & 1) + (e >> 2) * 8;
        float w;
        if (m < 128) w = out_w[(l * 128 + m) * 128 + r];
        else         w = out1_w[(m - 128) * (RR * NL) + l * 128 + r];
        __half hi = __float2half_rn(w);
        g_w2h[ii] = hi;
        g_w2l[ii] = __float2half_rn(w - __half2float(hi));
    }
}

__global__ void k_input(const float* __restrict__ x, const float* __restrict__ iw,
                        const float* __restrict__ ib, const float* __restrict__ ob1) {
    size_t idx = (size_t)blockIdx.x * blockDim.x + threadIdx.x;
    int t = (int)(idx % TS);
    size_t br = idx / TS;
    int r = (int)(br % RR);
    int b = (int)(br / RR);
    float v = tanhf(iw[r] * x[(size_t)b * TS + t] + ib[r]);
    g_h[0][idx] = v;
    g_skip[idx] = ob1[r];
}

// build hi/lo half2 pair regs from 2 fp32 scalars
__device__ __forceinline__ void mkb(float v0, float v1, uint32_t& bh, uint32_t& bl) {
    __half h0 = __float2half_rn(v0), h1 = __float2half_rn(v1);
    __half l0 = __float2half_rn(v0 - __half2float(h0));
    __half l1 = __float2half_rn(v1 - __half2float(h1));
    __half2 ph = __halves2half2(h0, h1), pl = __halves2half2(l0, l1);
    bh = *(uint32_t*)&ph;
    bl = *(uint32_t*)&pl;
}

__global__ __launch_bounds__(NTHR, 1)
void k_layer(int l, int parity,
             const float* __restrict__ conv_b, const float* __restrict__ out_b) {
    extern __shared__ __align__(16) float sm[];
    float* sA0 = sm;                  // 32*132
    float* sA1 = sm + 4224;
    float* sZ  = sm + 8448;           // 128*132
    float* cb  = sm + 25344;          // 256
    float* ob  = cb + 256;            // 128

    const int tid = threadIdx.x;
    const int lane = tid & 31;
    const int wid = tid >> 5;
    const int wm = wid >> 2;          // oc group
    const int wn = wid & 3;           // t group
    const int g = lane >> 2;
    const int q = lane & 3;
    const int tcb = wn * 32 + g;

    const int b = blockIdx.y;
    const int t0 = blockIdx.x * 128;
    const int dil = c_dil[l];

    const float* __restrict__ hin = g_h[parity] + (size_t)b * RR * TS;
    float* __restrict__ hout = g_h[parity ^ 1] + (size_t)b * RR * TS;
    float* __restrict__ skp = g_skip + (size_t)b * RR * TS;

    if (tid < 256) cb[tid] = conv_b[l * 256 + tid];
    else if (tid < 384) ob[tid - 256] = out_b[l * 128 + (tid - 256)];

    const int fr = tid >> 4;              // fill row 0..31
    const int tseg = (tid & 15) * 8;      // fill t-seg

    float acc[4][4][4];
#pragma unroll
    for (int mt = 0; mt < 4; mt++)
#pragma unroll
        for (int nt = 0; nt < 4; nt++)
#pragma unroll
            for (int e = 0; e < 4; e++) acc[mt][nt][e] = 0.f;

    // ---- prologue: fill chunk 0 (raw fp32) ----
    {
        int shift = -2 * dil;            // tap 0
        const float* src = hin + (size_t)fr * TS + t0 + shift + tseg;
        int tb = t0 + shift + tseg;
        float* dst = sA0 + fr * PAD + tseg;
#pragma unroll
        for (int j = 0; j < 8; j++) dst[j] = (tb + j >= 0) ? src[j] : 0.f;
    }
    __syncthreads();

    // ---- phase 1: D1[256 oc][128 t], K = 384 (12 chunks of 32) ----
    for (int c = 0; c < 12; c++) {
        float pv[8];
        const int have = (c < 11);
        if (have) {
            int c2 = c + 1;
            int tap2 = c2 >> 2, kc2 = c2 & 3;
            int shift = (tap2 - 2) * dil;
            const float* src = hin + (size_t)(kc2 * 32 + fr) * TS + t0 + shift + tseg;
            int tb = t0 + shift + tseg;
#pragma unroll
            for (int j = 0; j < 8; j++) pv[j] = (tb + j >= 0) ? src[j] : 0.f;
        }

        size_t choff = ((size_t)((l * 3 + (c >> 2)) * 4 + (c & 3))) * 8192 + wm * 2048;
        const __half* wh = g_w1h + choff;
        const __half* wl = g_w1l + choff;
        const float* bufp = (c & 1) ? sA1 : sA0;
#pragma unroll
        for (int ks = 0; ks < 2; ks++) {
            const float* p0 = bufp + (ks * 16 + 2 * q) * PAD + tcb;
            uint32_t b0h[4], b0l[4], b1h[4], b1l[4];
#pragma unroll
            for (int nt = 0; nt < 4; nt++) {
                mkb(p0[nt * 8], p0[PAD + nt * 8], b0h[nt], b0l[nt]);
                mkb(p0[8 * PAD + nt * 8], p0[9 * PAD + nt * 8], b1h[nt], b1l[nt]);
            }
#pragma unroll
            for (int mt = 0; mt < 4; mt++) {
                uint4 ah = ((const uint4*)(wh + ks * 1024 + mt * 256))[lane];
                uint4 al = ((const uint4*)(wl + ks * 1024 + mt * 256))[lane];
#pragma unroll
                for (int nt = 0; nt < 4; nt++) {
                    mma16(acc[mt][nt], ah, b0h[nt], b1h[nt]);
                    mma16(acc[mt][nt], ah, b0l[nt], b1l[nt]);
                    mma16(acc[mt][nt], al, b0h[nt], b1h[nt]);
                }
            }
        }

        if (have) {
            float* dst = ((c + 1) & 1 ? sA1 : sA0) + fr * PAD + tseg;
#pragma unroll
            for (int j = 0; j < 8; j++) dst[j] = pv[j];
        }
        __syncthreads();
    }

    // ---- epilogue 1: gate in-register -> z tile (raw fp32) ----
#pragma unroll
    for (int mt = 0; mt < 2; mt++) {
        int zc = wm * 32 + mt * 16 + g;
        float bt0 = cb[zc], bg0 = cb[128 + zc];
        float bt8 = cb[zc + 8], bg8 = cb[128 + zc + 8];
#pragma unroll
        for (int nt = 0; nt < 4; nt++) {
            int tc = wn * 32 + nt * 8 + 2 * q;
            float z0 = tanhf(acc[mt][nt][0] + bt0) * sigmoidf_(acc[mt + 2][nt][0] + bg0);
            float z1 = tanhf(acc[mt][nt][1] + bt0) * sigmoidf_(acc[mt + 2][nt][1] + bg0);
            *(float2*)(sZ + zc * PAD + tc) = make_float2(z0, z1);
            float z2 = tanhf(acc[mt][nt][2] + bt8) * sigmoidf_(acc[mt + 2][nt][2] + bg8);
            float z3 = tanhf(acc[mt][nt][3] + bt8) * sigmoidf_(acc[mt + 2][nt][3] + bg8);
            *(float2*)(sZ + (zc + 8) * PAD + tc) = make_float2(z2, z3);
        }
    }
    __syncthreads();

    // ---- phase 2: [res;skip][t] = W2 @ z, K = 128 (4 chunks of 32) ----
#pragma unroll
    for (int mt = 0; mt < 4; mt++)
#pragma unroll
        for (int nt = 0; nt < 4; nt++)
#pragma unroll
            for (int e = 0; e < 4; e++) acc[mt][nt][e] = 0.f;

    for (int kc = 0; kc < 4; kc++) {
        size_t choff = (size_t)(l * 4 + kc) * 8192 + wm * 2048;
        const __half* wh = g_w2h + choff;
        const __half* wl = g_w2l + choff;
#pragma unroll
        for (int ks = 0; ks < 2; ks++) {
            const float* p0 = sZ + (kc * 32 + ks * 16 + 2 * q) * PAD + tcb;
            uint32_t b0h[4], b0l[4], b1h[4], b1l[4];
#pragma unroll
            for (int nt = 0; nt < 4; nt++) {
                mkb(p0[nt * 8], p0[PAD + nt * 8], b0h[nt], b0l[nt]);
                mkb(p0[8 * PAD + nt * 8], p0[9 * PAD + nt * 8], b1h[nt], b1l[nt]);
            }
#pragma unroll
            for (int mt = 0; mt < 4; mt++) {
                uint4 ah = ((const uint4*)(wh + ks * 1024 + mt * 256))[lane];
                uint4 al = ((const uint4*)(wl + ks * 1024 + mt * 256))[lane];
#pragma unroll
                for (int nt = 0; nt < 4; nt++) {
                    mma16(acc[mt][nt], ah, b0h[nt], b1h[nt]);
                    mma16(acc[mt][nt], ah, b0l[nt], b1l[nt]);
                    mma16(acc[mt][nt], al, b0h[nt], b1h[nt]);
                }
            }
        }
    }

    // ---- epilogue 2: h_out = h_in + res + out_b ; skip += delta ----
#pragma unroll
    for (int mt = 0; mt < 2; mt++) {
        int r0 = wm * 32 + mt * 16 + g;
        float ob0 = ob[r0], ob8 = ob[r0 + 8];
#pragma unroll
        for (int nt = 0; nt < 4; nt++) {
            int tc = wn * 32 + nt * 8 + 2 * q;
            size_t ix = (size_t)r0 * TS + t0 + tc;
            size_t ix8 = ix + (size_t)8 * TS;

            float2 hv = *(const float2*)(hin + ix);
            *(float2*)(hout + ix) = make_float2(hv.x + acc[mt][nt][0] + ob0,
                                                hv.y + acc[mt][nt][1] + ob0);
            float2 hv8 = *(const float2*)(hin + ix8);
            *(float2*)(hout + ix8) = make_float2(hv8.x + acc[mt][nt][2] + ob8,
                                                 hv8.y + acc[mt][nt][3] + ob8);

            float2 sv = *(const float2*)(skp + ix);
            sv.x += acc[mt + 2][nt][0];
            sv.y += acc[mt + 2][nt][1];
            *(float2*)(skp + ix) = sv;
            float2 sv8 = *(const float2*)(skp + ix8);
            sv8.x += acc[mt + 2][nt][2];
            sv8.y += acc[mt + 2][nt][3];
            *(float2*)(skp + ix8) = sv8;
        }
    }
}

__global__ void k_out(const float* __restrict__ w2, const float* __restrict__ b2,
                      float* __restrict__ out) {
    int idx = blockIdx.x * blockDim.x + threadIdx.x;  // b*T + t
    int t = idx % TS;
    int b = idx / TS;
    const float* sp = g_skip + (size_t)b * RR * TS + t;
    float a = 0.f;
#pragma unroll 8
    for (int ro = 0; ro < RR; ro++) a += w2[ro] * tanhf(sp[(size_t)ro * TS]);
    out[idx] = a + b2[0];
}

extern "C" void kernel_launch(void* const* d_in, const int* in_sizes, int n_in,
                              void* d_out, int out_size) {
    const float* x       = (const float*)d_in[0];
    const float* input_w = (const float*)d_in[1];
    const float* input_b = (const float*)d_in[2];
    const float* conv_w  = (const float*)d_in[3];
    const float* conv_b  = (const float*)d_in[4];
    const float* out_w   = (const float*)d_in[5];
    const float* out_b   = (const float*)d_in[6];
    const float* out1_w  = (const float*)d_in[7];
    const float* out1_b  = (const float*)d_in[8];
    const float* out2_w  = (const float*)d_in[9];
    const float* out2_b  = (const float*)d_in[10];

    const int SMEM = 25728 * 4;  // 102912 bytes
    cudaFuncSetAttribute(k_layer, cudaFuncAttributeMaxDynamicSharedMemorySize, SMEM);

    int n_prep = NL * 12 * 8192 + NL * 4 * 8192;
    k_prep<<<(n_prep + 255) / 256, 256>>>(conv_w, out_w, out1_w);
    k_input<<<(BB * RR * TS) / 256, 256>>>(x, input_w, input_b, out1_b);

    int par = 0;
    for (int l = 0; l < NL; l++) {
        k_layer<<<dim3(TS / 128, BB), NTHR, SMEM>>>(l, par, conv_b, out_b);
        par ^= 1;
    }
    k_out<<<(BB * TS) / 256, 256>>>(out2_w, out2_b, (float*)d_out);
}

// round 8
// speedup vs baseline: 2.7819x; 1.0618x over previous
#include <cuda_runtime.h>
#include <cuda_fp16.h>
#include <math.h>
#include <stdint.h>

#define BB 8
#define RR 128
#define TS 16384
#define NL 9
#define NTHR 512

// operand tiles: packed half2 words, layout [kpair][t], pitch 136 words
#define PT 136

// ---- global scratch ----
__device__ __align__(16) float g_h[2][(size_t)BB * RR * TS];
__device__ __align__(16) float g_skip[(size_t)BB * RR * TS];
// fragment-permuted fp16 weights, hi/lo split (A operand layout)
__device__ __align__(16) __half g_w1h[NL * 12 * 8192];
__device__ __align__(16) __half g_w1l[NL * 12 * 8192];
__device__ __align__(16) __half g_w2h[NL * 4 * 8192];
__device__ __align__(16) __half g_w2l[NL * 4 * 8192];

__constant__ int c_dil[NL] = {1, 2, 4, 8, 16, 32, 64, 128, 256};

__device__ __forceinline__ float sigmoidf_(float x) { return 1.f / (1.f + __expf(-x)); }

__device__ __forceinline__ void mma16(float* d, uint4 a, uint32_t b0, uint32_t b1) {
    asm volatile("mma.sync.aligned.m16n8k16.row.col.f32.f16.f16.f32 "
                 "{%0,%1,%2,%3}, {%4,%5,%6,%7}, {%8,%9}, {%0,%1,%2,%3};"
                 : "+f"(d[0]), "+f"(d[1]), "+f"(d[2]), "+f"(d[3])
                 : "r"(a.x), "r"(a.y), "r"(a.z), "r"(a.w), "r"(b0), "r"(b1));
}

// pack 2 fp32 into hi/lo half2 words
__device__ __forceinline__ void mkb(float v0, float v1, uint32_t& bh, uint32_t& bl) {
    __half h0 = __float2half_rn(v0), h1 = __float2half_rn(v1);
    __half l0 = __float2half_rn(v0 - __half2float(h0));
    __half l1 = __float2half_rn(v1 - __half2float(h1));
    __half2 ph = __halves2half2(h0, h1), pl = __halves2half2(l0, l1);
    bh = *(uint32_t*)&ph;
    bl = *(uint32_t*)&pl;
}

// A-frag (f16 m16n8k16) element e in 0..7:  row = g + ((e>>1)&1)*8 ;  k = 2q + (e&1) + (e>>2)*8
// oc mapping: mt 0,1 -> low half, mt 2,3 -> +128.
__global__ void k_prep(const float* __restrict__ conv_w,
                       const float* __restrict__ out_w,
                       const float* __restrict__ out1_w) {
    int i = blockIdx.x * blockDim.x + threadIdx.x;
    const int n1 = NL * 12 * 8192;
    const int n2 = NL * 4 * 8192;
    if (i < n1) {
        int j = i & 8191;
        int ci = i >> 13;            // (l*3+tap)*4 + kc
        int kc = ci & 3;
        int tap = (ci >> 2) % 3;
        int l = ci / 12;
        int e = j & 7, lane = (j >> 3) & 31, mt = (j >> 8) & 3, ks = (j >> 10) & 1, og = (j >> 11) & 3;
        int g = lane >> 2, q = lane & 3;
        int oc = og * 32 + (mt & 1) * 16 + (mt >> 1) * 128 + g + ((e >> 1) & 1) * 8;
        int r = kc * 32 + ks * 16 + 2 * q + (e & 1) + (e >> 2) * 8;
        float w = conv_w[((l * 256 + oc) * 128 + r) * 3 + tap];
        __half hi = __float2half_rn(w);
        g_w1h[i] = hi;
        g_w1l[i] = __float2half_rn(w - __half2float(hi));
    } else if (i < n1 + n2) {
        int ii = i - n1;
        int j = ii & 8191;
        int ci = ii >> 13;           // l*4 + kc
        int kc = ci & 3;
        int l = ci >> 2;
        int e = j & 7, lane = (j >> 3) & 31, mt = (j >> 8) & 3, ks = (j >> 10) & 1, og = (j >> 11) & 3;
        int g = lane >> 2, q = lane & 3;
        int m = og * 32 + (mt & 1) * 16 + (mt >> 1) * 128 + g + ((e >> 1) & 1) * 8;
        // phase-2 K is permuted: slot 2s -> ch (s>>4)*32+((s>>3)&1)*16+(s&7); slot 2s+1 -> +8
        int k = kc * 32 + ks * 16 + 2 * q + (e & 1) + (e >> 2) * 8;
        int s = k >> 1, odd = k & 1;
        int r = (s >> 4) * 32 + ((s >> 3) & 1) * 16 + (s & 7) + odd * 8;
        float w;
        if (m < 128) w = out_w[(l * 128 + m) * 128 + r];
        else         w = out1_w[(m - 128) * (RR * NL) + l * 128 + r];
        __half hi = __float2half_rn(w);
        g_w2h[ii] = hi;
        g_w2l[ii] = __float2half_rn(w - __half2float(hi));
    }
}

__global__ void k_input(const float* __restrict__ x, const float* __restrict__ iw,
                        const float* __restrict__ ib, const float* __restrict__ ob1) {
    size_t idx = (size_t)blockIdx.x * blockDim.x + threadIdx.x;
    int t = (int)(idx % TS);
    size_t br = idx / TS;
    int r = (int)(br % RR);
    int b = (int)(br / RR);
    float v = tanhf(iw[r] * x[(size_t)b * TS + t] + ib[r]);
    g_h[0][idx] = v;
    g_skip[idx] = ob1[r];
}

// SMEM word offsets
#define OAH0 0u
#define OAL0 2176u
#define OAH1 4352u
#define OAL1 6528u
#define OZH  8704u
#define OZL  17408u
#define OCB  26112u
#define OOB  26368u
#define SMW  26496u

__global__ __launch_bounds__(NTHR, 1)
void k_layer(int l, int parity,
             const float* __restrict__ conv_b, const float* __restrict__ out_b) {
    extern __shared__ __align__(16) uint32_t sw[];
    float* cb = (float*)(sw + OCB);
    float* ob = (float*)(sw + OOB);

    const int tid = threadIdx.x;
    const int lane = tid & 31;
    const int wid = tid >> 5;
    const int wm = wid >> 2;          // oc group
    const int wn = wid & 3;           // t group
    const int g = lane >> 2;
    const int q = lane & 3;
    const int tcb = wn * 32 + g;

    const int b = blockIdx.y;
    const int t0 = blockIdx.x * 128;
    const int dil = c_dil[l];

    const float* __restrict__ hin = g_h[parity] + (size_t)b * RR * TS;
    float* __restrict__ hout = g_h[parity ^ 1] + (size_t)b * RR * TS;
    float* __restrict__ skp = g_skip + (size_t)b * RR * TS;

    if (tid < 256) cb[tid] = conv_b[l * 256 + tid];
    else if (tid < 384) ob[tid - 256] = out_b[l * 128 + (tid - 256)];

    // fill mapping: thread owns kpair kp (rows 2kp,2kp+1) x 4 t (tg + j*32)
    const int kp = tid >> 5;          // 0..15
    const int tg = tid & 31;

    float acc[4][4][4];
#pragma unroll
    for (int mt = 0; mt < 4; mt++)
#pragma unroll
        for (int nt = 0; nt < 4; nt++)
#pragma unroll
            for (int e = 0; e < 4; e++) acc[mt][nt][e] = 0.f;

    // ---- prologue: fill chunk 0 into buf0 ----
    {
        int shift = -2 * dil;            // tap 0, kc 0
        const float* r0p = hin + (size_t)(2 * kp) * TS + t0 + shift;
        const float* r1p = r0p + TS;
#pragma unroll
        for (int j = 0; j < 4; j++) {
            int t = tg + j * 32;
            int tb = t0 + shift + t;
            float v0 = (tb >= 0) ? r0p[t] : 0.f;
            float v1 = (tb >= 0) ? r1p[t] : 0.f;
            uint32_t hw, lw;
            mkb(v0, v1, hw, lw);
            sw[OAH0 + kp * PT + t] = hw;
            sw[OAL0 + kp * PT + t] = lw;
        }
    }
    __syncthreads();

    // ---- phase 1: D1[256 oc][128 t], K = 384 (12 chunks of 32) ----
    for (int c = 0; c < 12; c++) {
        float pv0[4], pv1[4];
        const int have = (c < 11);
        if (have) {
            int c2 = c + 1;
            int tap2 = c2 >> 2, kc2 = c2 & 3;
            int shift = (tap2 - 2) * dil;
            const float* r0p = hin + (size_t)(kc2 * 32 + 2 * kp) * TS + t0 + shift;
            const float* r1p = r0p + TS;
#pragma unroll
            for (int j = 0; j < 4; j++) {
                int t = tg + j * 32;
                int tb = t0 + shift + t;
                pv0[j] = (tb >= 0) ? r0p[t] : 0.f;
                pv1[j] = (tb >= 0) ? r1p[t] : 0.f;
            }
        }

        size_t choff = ((size_t)((l * 3 + (c >> 2)) * 4 + (c & 3))) * 8192 + wm * 2048;
        const __half* wh = g_w1h + choff;
        const __half* wl = g_w1l + choff;
        const uint32_t* bh = sw + ((c & 1) ? OAH1 : OAH0);
        const uint32_t* bl = sw + ((c & 1) ? OAL1 : OAL0);
#pragma unroll
        for (int ks = 0; ks < 2; ks++) {
            uint32_t base = (uint32_t)(ks * 8 + q) * PT + tcb;
            uint32_t b0h[4], b0l[4], b1h[4], b1l[4];
#pragma unroll
            for (int nt = 0; nt < 4; nt++) {
                b0h[nt] = bh[base + nt * 8];
                b1h[nt] = bh[base + 4 * PT + nt * 8];
                b0l[nt] = bl[base + nt * 8];
                b1l[nt] = bl[base + 4 * PT + nt * 8];
            }
#pragma unroll
            for (int mt = 0; mt < 4; mt++) {
                uint4 ah = ((const uint4*)(wh + ks * 1024 + mt * 256))[lane];
                uint4 al = ((const uint4*)(wl + ks * 1024 + mt * 256))[lane];
#pragma unroll
                for (int nt = 0; nt < 4; nt++) {
                    mma16(acc[mt][nt], ah, b0h[nt], b1h[nt]);
                    mma16(acc[mt][nt], ah, b0l[nt], b1l[nt]);
                    mma16(acc[mt][nt], al, b0h[nt], b1h[nt]);
                }
            }
        }

        if (have) {
            uint32_t dh = ((c + 1) & 1) ? OAH1 : OAH0;
            uint32_t dl = ((c + 1) & 1) ? OAL1 : OAL0;
#pragma unroll
            for (int j = 0; j < 4; j++) {
                int t = tg + j * 32;
                uint32_t hw, lw;
                mkb(pv0[j], pv1[j], hw, lw);
                sw[dh + kp * PT + t] = hw;
                sw[dl + kp * PT + t] = lw;
            }
        }
        __syncthreads();
    }

    // ---- epilogue 1: gate -> z tile as half2 hi/lo, K-slot pair (zc, zc+8) ----
#pragma unroll
    for (int mt = 0; mt < 2; mt++) {
        int zc = wm * 32 + mt * 16 + g;
        int s = wm * 16 + mt * 8 + g;     // kpair slot
        float bt0 = cb[zc], bg0 = cb[128 + zc];
        float bt8 = cb[zc + 8], bg8 = cb[128 + zc + 8];
#pragma unroll
        for (int nt = 0; nt < 4; nt++) {
            int tc = wn * 32 + nt * 8 + 2 * q;
            float zA0 = tanhf(acc[mt][nt][0] + bt0) * sigmoidf_(acc[mt + 2][nt][0] + bg0);
            float zA1 = tanhf(acc[mt][nt][1] + bt0) * sigmoidf_(acc[mt + 2][nt][1] + bg0);
            float zB0 = tanhf(acc[mt][nt][2] + bt8) * sigmoidf_(acc[mt + 2][nt][2] + bg8);
            float zB1 = tanhf(acc[mt][nt][3] + bt8) * sigmoidf_(acc[mt + 2][nt][3] + bg8);
            uint32_t hw, lw;
            mkb(zA0, zB0, hw, lw);
            sw[OZH + s * PT + tc] = hw;
            sw[OZL + s * PT + tc] = lw;
            mkb(zA1, zB1, hw, lw);
            sw[OZH + s * PT + tc + 1] = hw;
            sw[OZL + s * PT + tc + 1] = lw;
        }
    }
    __syncthreads();

    // ---- phase 2: [res;skip][t] = W2 @ z (K permuted), K = 128 ----
#pragma unroll
    for (int mt = 0; mt < 4; mt++)
#pragma unroll
        for (int nt = 0; nt < 4; nt++)
#pragma unroll
            for (int e = 0; e < 4; e++) acc[mt][nt][e] = 0.f;

    for (int kc = 0; kc < 4; kc++) {
        size_t choff = (size_t)(l * 4 + kc) * 8192 + wm * 2048;
        const __half* wh = g_w2h + choff;
        const __half* wl = g_w2l + choff;
#pragma unroll
        for (int ks = 0; ks < 2; ks++) {
            uint32_t base = (uint32_t)(kc * 16 + ks * 8 + q) * PT + tcb;
            uint32_t b0h[4], b0l[4], b1h[4], b1l[4];
#pragma unroll
            for (int nt = 0; nt < 4; nt++) {
                b0h[nt] = sw[OZH + base + nt * 8];
                b1h[nt] = sw[OZH + base + 4 * PT + nt * 8];
                b0l[nt] = sw[OZL + base + nt * 8];
                b1l[nt] = sw[OZL + base + 4 * PT + nt * 8];
            }
#pragma unroll
            for (int mt = 0; mt < 4; mt++) {
                uint4 ah = ((const uint4*)(wh + ks * 1024 + mt * 256))[lane];
                uint4 al = ((const uint4*)(wl + ks * 1024 + mt * 256))[lane];
#pragma unroll
                for (int nt = 0; nt < 4; nt++) {
                    mma16(acc[mt][nt], ah, b0h[nt], b1h[nt]);
                    mma16(acc[mt][nt], ah, b0l[nt], b1l[nt]);
                    mma16(acc[mt][nt], al, b0h[nt], b1h[nt]);
                }
            }
        }
    }

    // ---- epilogue 2: h_out = h_in + res + out_b ; skip += delta ----
#pragma unroll
    for (int mt = 0; mt < 2; mt++) {
        int r0 = wm * 32 + mt * 16 + g;
        float ob0 = ob[r0], ob8 = ob[r0 + 8];
#pragma unroll
        for (int nt = 0; nt < 4; nt++) {
            int tc = wn * 32 + nt * 8 + 2 * q;
            size_t ix = (size_t)r0 * TS + t0 + tc;
            size_t ix8 = ix + (size_t)8 * TS;

            float2 hv = *(const float2*)(hin + ix);
            *(float2*)(hout + ix) = make_float2(hv.x + acc[mt][nt][0] + ob0,
                                                hv.y + acc[mt][nt][1] + ob0);
            float2 hv8 = *(const float2*)(hin + ix8);
            *(float2*)(hout + ix8) = make_float2(hv8.x + acc[mt][nt][2] + ob8,
                                                 hv8.y + acc[mt][nt][3] + ob8);

            float2 sv = *(const float2*)(skp + ix);
            sv.x += acc[mt + 2][nt][0];
            sv.y += acc[mt + 2][nt][1];
            *(float2*)(skp + ix) = sv;
            float2 sv8 = *(const float2*)(skp + ix8);
            sv8.x += acc[mt + 2][nt][2];
            sv8.y += acc[mt + 2][nt][3];
            *(float2*)(skp + ix8) = sv8;
        }
    }
}

__global__ void k_out(const float* __restrict__ w2, const float* __restrict__ b2,
                      float* __restrict__ out) {
    int idx = blockIdx.x * blockDim.x + threadIdx.x;  // b*T + t
    int t = idx % TS;
    int b = idx / TS;
    const float* sp = g_skip + (size_t)b * RR * TS + t;
    float a = 0.f;
#pragma unroll 8
    for (int ro = 0; ro < RR; ro++) a += w2[ro] * tanhf(sp[(size_t)ro * TS]);
    out[idx] = a + b2[0];
}

extern "C" void kernel_launch(void* const* d_in, const int* in_sizes, int n_in,
                              void* d_out, int out_size) {
    const float* x       = (const float*)d_in[0];
    const float* input_w = (const float*)d_in[1];
    const float* input_b = (const float*)d_in[2];
    const float* conv_w  = (const float*)d_in[3];
    const float* conv_b  = (const float*)d_in[4];
    const float* out_w   = (const float*)d_in[5];
    const float* out_b   = (const float*)d_in[6];
    const float* out1_w  = (const float*)d_in[7];
    const float* out1_b  = (const float*)d_in[8];
    const float* out2_w  = (const float*)d_in[9];
    const float* out2_b  = (const float*)d_in[10];

    const int SMEM = SMW * 4;  // 105984 bytes
    cudaFuncSetAttribute(k_layer, cudaFuncAttributeMaxDynamicSharedMemorySize, SMEM);

    int n_prep = NL * 12 * 8192 + NL * 4 * 8192;
    k_prep<<<(n_prep + 255) / 256, 256>>>(conv_w, out_w, out1_w);
    k_input<<<(BB * RR * TS) / 256, 256>>>(x, input_w, input_b, out1_b);

    int par = 0;
    for (int l = 0; l < NL; l++) {
        k_layer<<<dim3(TS / 128, BB), NTHR, SMEM>>>(l, par, conv_b, out_b);
        par ^= 1;
    }
    k_out<<<(BB * TS) / 256, 256>>>(out2_w, out2_b, (float*)d_out);
}

// round 9
// speedup vs baseline: 2.9638x; 1.0654x over previous
#include <cuda_runtime.h>
#include <cuda_fp16.h>
#include <math.h>
#include <stdint.h>

#define BB 8
#define RR 128
#define TS 16384
#define NL 9
#define NTHR 256

// operand tiles: packed half2 words, layout [kpair][t], 64-t tile, pitch 72 words
#define PT 72

// ---- global scratch ----
__device__ __align__(16) float g_h[2][(size_t)BB * RR * TS];
__device__ __align__(16) float g_skip[(size_t)BB * RR * TS];
// fragment-permuted fp16 weights, hi/lo split (A operand layout)
__device__ __align__(16) __half g_w1h[NL * 12 * 8192];
__device__ __align__(16) __half g_w1l[NL * 12 * 8192];
__device__ __align__(16) __half g_w2h[NL * 4 * 8192];
__device__ __align__(16) __half g_w2l[NL * 4 * 8192];

__constant__ int c_dil[NL] = {1, 2, 4, 8, 16, 32, 64, 128, 256};

__device__ __forceinline__ float sigmoidf_(float x) { return 1.f / (1.f + __expf(-x)); }

__device__ __forceinline__ void mma16(float* d, uint4 a, uint32_t b0, uint32_t b1) {
    asm volatile("mma.sync.aligned.m16n8k16.row.col.f32.f16.f16.f32 "
                 "{%0,%1,%2,%3}, {%4,%5,%6,%7}, {%8,%9}, {%0,%1,%2,%3};"
                 : "+f"(d[0]), "+f"(d[1]), "+f"(d[2]), "+f"(d[3])
                 : "r"(a.x), "r"(a.y), "r"(a.z), "r"(a.w), "r"(b0), "r"(b1));
}

// pack 2 fp32 into hi/lo half2 words
__device__ __forceinline__ void mkb(float v0, float v1, uint32_t& bh, uint32_t& bl) {
    __half h0 = __float2half_rn(v0), h1 = __float2half_rn(v1);
    __half l0 = __float2half_rn(v0 - __half2float(h0));
    __half l1 = __float2half_rn(v1 - __half2float(h1));
    __half2 ph = __halves2half2(h0, h1), pl = __halves2half2(l0, l1);
    bh = *(uint32_t*)&ph;
    bl = *(uint32_t*)&pl;
}

// A-frag (f16 m16n8k16) element e in 0..7:  row = g + ((e>>1)&1)*8 ;  k = 2q + (e&1) + (e>>2)*8
// oc mapping: mt 0,1 -> low half, mt 2,3 -> +128.
__global__ void k_prep(const float* __restrict__ conv_w,
                       const float* __restrict__ out_w,
                       const float* __restrict__ out1_w) {
    int i = blockIdx.x * blockDim.x + threadIdx.x;
    const int n1 = NL * 12 * 8192;
    const int n2 = NL * 4 * 8192;
    if (i < n1) {
        int j = i & 8191;
        int ci = i >> 13;            // (l*3+tap)*4 + kc
        int kc = ci & 3;
        int tap = (ci >> 2) % 3;
        int l = ci / 12;
        int e = j & 7, lane = (j >> 3) & 31, mt = (j >> 8) & 3, ks = (j >> 10) & 1, og = (j >> 11) & 3;
        int g = lane >> 2, q = lane & 3;
        int oc = og * 32 + (mt & 1) * 16 + (mt >> 1) * 128 + g + ((e >> 1) & 1) * 8;
        int r = kc * 32 + ks * 16 + 2 * q + (e & 1) + (e >> 2) * 8;
        float w = conv_w[((l * 256 + oc) * 128 + r) * 3 + tap];
        __half hi = __float2half_rn(w);
        g_w1h[i] = hi;
        g_w1l[i] = __float2half_rn(w - __half2float(hi));
    } else if (i < n1 + n2) {
        int ii = i - n1;
        int j = ii & 8191;
        int ci = ii >> 13;           // l*4 + kc
        int kc = ci & 3;
        int l = ci >> 2;
        int e = j & 7, lane = (j >> 3) & 31, mt = (j >> 8) & 3, ks = (j >> 10) & 1, og = (j >> 11) & 3;
        int g = lane >> 2, q = lane & 3;
        int m = og * 32 + (mt & 1) * 16 + (mt >> 1) * 128 + g + ((e >> 1) & 1) * 8;
        // phase-2 K is permuted: slot 2s -> ch (s>>4)*32+((s>>3)&1)*16+(s&7); slot 2s+1 -> +8
        int k = kc * 32 + ks * 16 + 2 * q + (e & 1) + (e >> 2) * 8;
        int s = k >> 1, odd = k & 1;
        int r = (s >> 4) * 32 + ((s >> 3) & 1) * 16 + (s & 7) + odd * 8;
        float w;
        if (m < 128) w = out_w[(l * 128 + m) * 128 + r];
        else         w = out1_w[(m - 128) * (RR * NL) + l * 128 + r];
        __half hi = __float2half_rn(w);
        g_w2h[ii] = hi;
        g_w2l[ii] = __float2half_rn(w - __half2float(hi));
    }
}

__global__ void k_input(const float* __restrict__ x, const float* __restrict__ iw,
                        const float* __restrict__ ib, const float* __restrict__ ob1) {
    size_t idx = (size_t)blockIdx.x * blockDim.x + threadIdx.x;
    int t = (int)(idx % TS);
    size_t br = idx / TS;
    int r = (int)(br % RR);
    int b = (int)(br / RR);
    float v = tanhf(iw[r] * x[(size_t)b * TS + t] + ib[r]);
    g_h[0][idx] = v;
    g_skip[idx] = ob1[r];
}

// SMEM word offsets (words)
#define OAH0 0u
#define OAL0 1152u
#define OAH1 2304u
#define OAL1 3456u
#define OZH  4608u
#define OZL  9216u
#define OCB  13824u
#define OOB  14080u
#define SMW  14208u

__global__ __launch_bounds__(NTHR, 2)
void k_layer(int l, int parity,
             const float* __restrict__ conv_b, const float* __restrict__ out_b) {
    extern __shared__ __align__(16) uint32_t sw[];
    float* cb = (float*)(sw + OCB);
    float* ob = (float*)(sw + OOB);

    const int tid = threadIdx.x;
    const int lane = tid & 31;
    const int wid = tid >> 5;
    const int wm = wid >> 1;          // oc group 0..3
    const int wn = wid & 1;           // t group 0..1
    const int g = lane >> 2;
    const int q = lane & 3;
    const int tcb = wn * 32 + g;

    const int b = blockIdx.y;
    const int t0 = blockIdx.x * 64;
    const int dil = c_dil[l];

    const float* __restrict__ hin = g_h[parity] + (size_t)b * RR * TS;
    float* __restrict__ hout = g_h[parity ^ 1] + (size_t)b * RR * TS;
    float* __restrict__ skp = g_skip + (size_t)b * RR * TS;

    if (tid < 256) cb[tid] = conv_b[l * 256 + tid];
    if (tid < 128) ob[tid] = out_b[l * 128 + tid];

    // fill mapping: thread owns kpair kp (rows 2kp,2kp+1) x 4 t (tg + j*16)
    const int kp = tid >> 4;          // 0..15
    const int tg = tid & 15;

    float acc[4][4][4];
#pragma unroll
    for (int mt = 0; mt < 4; mt++)
#pragma unroll
        for (int nt = 0; nt < 4; nt++)
#pragma unroll
            for (int e = 0; e < 4; e++) acc[mt][nt][e] = 0.f;

    // ---- prologue: fill chunk 0 into buf0 ----
    {
        int shift = -2 * dil;            // tap 0, kc 0
        const float* r0p = hin + (size_t)(2 * kp) * TS + t0 + shift;
        const float* r1p = r0p + TS;
#pragma unroll
        for (int j = 0; j < 4; j++) {
            int t = tg + j * 16;
            int tb = t0 + shift + t;
            float v0 = (tb >= 0) ? r0p[t] : 0.f;
            float v1 = (tb >= 0) ? r1p[t] : 0.f;
            uint32_t hw, lw;
            mkb(v0, v1, hw, lw);
            sw[OAH0 + kp * PT + t] = hw;
            sw[OAL0 + kp * PT + t] = lw;
        }
    }
    __syncthreads();

    // ---- phase 1: D1[256 oc][64 t], K = 384 (12 chunks of 32) ----
    for (int c = 0; c < 12; c++) {
        float pv0[4], pv1[4];
        const int have = (c < 11);
        if (have) {
            int c2 = c + 1;
            int tap2 = c2 >> 2, kc2 = c2 & 3;
            int shift = (tap2 - 2) * dil;
            const float* r0p = hin + (size_t)(kc2 * 32 + 2 * kp) * TS + t0 + shift;
            const float* r1p = r0p + TS;
#pragma unroll
            for (int j = 0; j < 4; j++) {
                int t = tg + j * 16;
                int tb = t0 + shift + t;
                pv0[j] = (tb >= 0) ? r0p[t] : 0.f;
                pv1[j] = (tb >= 0) ? r1p[t] : 0.f;
            }
        }

        size_t choff = ((size_t)((l * 3 + (c >> 2)) * 4 + (c & 3))) * 8192 + wm * 2048;
        const __half* wh = g_w1h + choff;
        const __half* wl = g_w1l + choff;
        const uint32_t* bh = sw + ((c & 1) ? OAH1 : OAH0);
        const uint32_t* bl = sw + ((c & 1) ? OAL1 : OAL0);
#pragma unroll
        for (int ks = 0; ks < 2; ks++) {
            uint32_t base = (uint32_t)(ks * 8 + q) * PT + tcb;
            uint32_t b0h[4], b0l[4], b1h[4], b1l[4];
#pragma unroll
            for (int nt = 0; nt < 4; nt++) {
                b0h[nt] = bh[base + nt * 8];
                b1h[nt] = bh[base + 4 * PT + nt * 8];
                b0l[nt] = bl[base + nt * 8];
                b1l[nt] = bl[base + 4 * PT + nt * 8];
            }
#pragma unroll
            for (int mt = 0; mt < 4; mt++) {
                uint4 ah = ((const uint4*)(wh + ks * 1024 + mt * 256))[lane];
                uint4 al = ((const uint4*)(wl + ks * 1024 + mt * 256))[lane];
#pragma unroll
                for (int nt = 0; nt < 4; nt++) {
                    mma16(acc[mt][nt], ah, b0h[nt], b1h[nt]);
                    mma16(acc[mt][nt], ah, b0l[nt], b1l[nt]);
                    mma16(acc[mt][nt], al, b0h[nt], b1h[nt]);
                }
            }
        }

        if (have) {
            uint32_t dh = ((c + 1) & 1) ? OAH1 : OAH0;
            uint32_t dl = ((c + 1) & 1) ? OAL1 : OAL0;
#pragma unroll
            for (int j = 0; j < 4; j++) {
                int t = tg + j * 16;
                uint32_t hw, lw;
                mkb(pv0[j], pv1[j], hw, lw);
                sw[dh + kp * PT + t] = hw;
                sw[dl + kp * PT + t] = lw;
            }
        }
        __syncthreads();
    }

    // ---- epilogue 1: gate -> z tile as half2 hi/lo, K-slot pair (zc, zc+8) ----
#pragma unroll
    for (int mt = 0; mt < 2; mt++) {
        int zc = wm * 32 + mt * 16 + g;
        int s = wm * 16 + mt * 8 + g;     // kpair slot
        float bt0 = cb[zc], bg0 = cb[128 + zc];
        float bt8 = cb[zc + 8], bg8 = cb[128 + zc + 8];
#pragma unroll
        for (int nt = 0; nt < 4; nt++) {
            int tc = wn * 32 + nt * 8 + 2 * q;
            float zA0 = tanhf(acc[mt][nt][0] + bt0) * sigmoidf_(acc[mt + 2][nt][0] + bg0);
            float zA1 = tanhf(acc[mt][nt][1] + bt0) * sigmoidf_(acc[mt + 2][nt][1] + bg0);
            float zB0 = tanhf(acc[mt][nt][2] + bt8) * sigmoidf_(acc[mt + 2][nt][2] + bg8);
            float zB1 = tanhf(acc[mt][nt][3] + bt8) * sigmoidf_(acc[mt + 2][nt][3] + bg8);
            uint32_t hw, lw;
            mkb(zA0, zB0, hw, lw);
            sw[OZH + s * PT + tc] = hw;
            sw[OZL + s * PT + tc] = lw;
            mkb(zA1, zB1, hw, lw);
            sw[OZH + s * PT + tc + 1] = hw;
            sw[OZL + s * PT + tc + 1] = lw;
        }
    }
    __syncthreads();

    // ---- phase 2: [res;skip][t] = W2 @ z (K permuted), K = 128 ----
#pragma unroll
    for (int mt = 0; mt < 4; mt++)
#pragma unroll
        for (int nt = 0; nt < 4; nt++)
#pragma unroll
            for (int e = 0; e < 4; e++) acc[mt][nt][e] = 0.f;

    for (int kc = 0; kc < 4; kc++) {
        size_t choff = (size_t)(l * 4 + kc) * 8192 + wm * 2048;
        const __half* wh = g_w2h + choff;
        const __half* wl = g_w2l + choff;
#pragma unroll
        for (int ks = 0; ks < 2; ks++) {
            uint32_t base = (uint32_t)(kc * 16 + ks * 8 + q) * PT + tcb;
            uint32_t b0h[4], b0l[4], b1h[4], b1l[4];
#pragma unroll
            for (int nt = 0; nt < 4; nt++) {
                b0h[nt] = sw[OZH + base + nt * 8];
                b1h[nt] = sw[OZH + base + 4 * PT + nt * 8];
                b0l[nt] = sw[OZL + base + nt * 8];
                b1l[nt] = sw[OZL + base + 4 * PT + nt * 8];
            }
#pragma unroll
            for (int mt = 0; mt < 4; mt++) {
                uint4 ah = ((const uint4*)(wh + ks * 1024 + mt * 256))[lane];
                uint4 al = ((const uint4*)(wl + ks * 1024 + mt * 256))[lane];
#pragma unroll
                for (int nt = 0; nt < 4; nt++) {
                    mma16(acc[mt][nt], ah, b0h[nt], b1h[nt]);
                    mma16(acc[mt][nt], ah, b0l[nt], b1l[nt]);
                    mma16(acc[mt][nt], al, b0h[nt], b1h[nt]);
                }
            }
        }
    }

    // ---- epilogue 2: h_out = h_in + res + out_b ; skip += delta ----
#pragma unroll
    for (int mt = 0; mt < 2; mt++) {
        int r0 = wm * 32 + mt * 16 + g;
        float ob0 = ob[r0], ob8 = ob[r0 + 8];
#pragma unroll
        for (int nt = 0; nt < 4; nt++) {
            int tc = wn * 32 + nt * 8 + 2 * q;
            size_t ix = (size_t)r0 * TS + t0 + tc;
            size_t ix8 = ix + (size_t)8 * TS;

            float2 hv = *(const float2*)(hin + ix);
            *(float2*)(hout + ix) = make_float2(hv.x + acc[mt][nt][0] + ob0,
                                                hv.y + acc[mt][nt][1] + ob0);
            float2 hv8 = *(const float2*)(hin + ix8);
            *(float2*)(hout + ix8) = make_float2(hv8.x + acc[mt][nt][2] + ob8,
                                                 hv8.y + acc[mt][nt][3] + ob8);

            float2 sv = *(const float2*)(skp + ix);
            sv.x += acc[mt + 2][nt][0];
            sv.y += acc[mt + 2][nt][1];
            *(float2*)(skp + ix) = sv;
            float2 sv8 = *(const float2*)(skp + ix8);
            sv8.x += acc[mt + 2][nt][2];
            sv8.y += acc[mt + 2][nt][3];
            *(float2*)(skp + ix8) = sv8;
        }
    }
}

__global__ void k_out(const float* __restrict__ w2, const float* __restrict__ b2,
                      float* __restrict__ out) {
    int idx = blockIdx.x * blockDim.x + threadIdx.x;  // b*T + t
    int t = idx % TS;
    int b = idx / TS;
    const float* sp = g_skip + (size_t)b * RR * TS + t;
    float a = 0.f;
#pragma unroll 8
    for (int ro = 0; ro < RR; ro++) a += w2[ro] * tanhf(sp[(size_t)ro * TS]);
    out[idx] = a + b2[0];
}

extern "C" void kernel_launch(void* const* d_in, const int* in_sizes, int n_in,
                              void* d_out, int out_size) {
    const float* x       = (const float*)d_in[0];
    const float* input_w = (const float*)d_in[1];
    const float* input_b = (const float*)d_in[2];
    const float* conv_w  = (const float*)d_in[3];
    const float* conv_b  = (const float*)d_in[4];
    const float* out_w   = (const float*)d_in[5];
    const float* out_b   = (const float*)d_in[6];
    const float* out1_w  = (const float*)d_in[7];
    const float* out1_b  = (const float*)d_in[8];
    const float* out2_w  = (const float*)d_in[9];
    const float* out2_b  = (const float*)d_in[10];

    const int SMEM = SMW * 4;  // 56832 bytes -> 2 CTAs/SM
    cudaFuncSetAttribute(k_layer, cudaFuncAttributeMaxDynamicSharedMemorySize, SMEM);

    int n_prep = NL * 12 * 8192 + NL * 4 * 8192;
    k_prep<<<(n_prep + 255) / 256, 256>>>(conv_w, out_w, out1_w);
    k_input<<<(BB * RR * TS) / 256, 256>>>(x, input_w, input_b, out1_b);

    int par = 0;
    for (int l = 0; l < NL; l++) {
        k_layer<<<dim3(TS / 64, BB), NTHR, SMEM>>>(l, par, conv_b, out_b);
        par ^= 1;
    }
    k_out<<<(BB * TS) / 256, 256>>>(out2_w, out2_b, (float*)d_out);
}